// round 1
// baseline (speedup 1.0000x reference)
#include <cuda_runtime.h>
#include <math.h>

// Problem constants
#define BB 16
#define LL 512
#define DD 128
#define SPITCH 132                 // padded row pitch (floats) for bank-conflict-free frags

// Scratch (device globals; no allocation allowed)
__device__ float g_kphi[BB * LL * DD];
__device__ float g_qphi[BB * LL * DD];
__device__ float g_y[BB * LL * DD];

// -------------------------------------------------------------------------
// mma.sync m16n8k8 tf32 (fallback HMMA path on sm_103a)
// -------------------------------------------------------------------------
__device__ __forceinline__ void mma8(float* c,
                                     unsigned a0, unsigned a1, unsigned a2, unsigned a3,
                                     unsigned b0, unsigned b1) {
    asm volatile(
        "mma.sync.aligned.m16n8k8.row.col.f32.tf32.tf32.f32 "
        "{%0,%1,%2,%3},{%4,%5,%6,%7},{%8,%9},{%0,%1,%2,%3};\n"
        : "+f"(c[0]), "+f"(c[1]), "+f"(c[2]), "+f"(c[3])
        : "r"(a0), "r"(a1), "r"(a2), "r"(a3), "r"(b0), "r"(b1));
}

// -------------------------------------------------------------------------
// Prepass: q/k projections + normalize + QKProjection(tanh) + poly features
// grid (L, B), 128 threads; thread e computes output feature e for (b,l)
// -------------------------------------------------------------------------
__global__ void prepass_kernel(const float* __restrict__ x,
                               const float* __restrict__ Wq,
                               const float* __restrict__ Wk,
                               const float* __restrict__ P0,
                               const float* __restrict__ log_gain,
                               const float* __restrict__ coeffs) {
    const int l = blockIdx.x, b = blockIdx.y;
    const int e = threadIdx.x;
    __shared__ float xs[DD];
    __shared__ float qraw[DD];
    __shared__ float red[4];

    const float* xp = x + (b * LL + l) * DD;
    xs[e] = xp[e];
    __syncthreads();

    float qr = 0.f, kr = 0.f;
    const float* wqr = Wq + e * DD;
    const float* wkr = Wk + e * DD;
#pragma unroll 8
    for (int d = 0; d < DD; ++d) {
        float xv = xs[d];
        qr += xv * wqr[d];
        kr += xv * wkr[d];
    }
    qraw[e] = qr;

    // ||k||_2 reduction (deterministic tree)
    float ps = kr * kr;
#pragma unroll
    for (int o = 16; o; o >>= 1) ps += __shfl_xor_sync(0xffffffffu, ps, o);
    if ((e & 31) == 0) red[e >> 5] = ps;
    __syncthreads();
    float nrm = sqrtf(red[0] + red[1] + red[2] + red[3]);
    float kn = kr / fmaxf(nrm, 1e-12f);

    const float c0 = coeffs[0], c1 = coeffs[1];
    g_kphi[(b * LL + l) * DD + e] = c0 * kn + c1 * kn * kn;

    // q_aligned = tanh(gain * (q @ P0))
    float qp = 0.f;
#pragma unroll 8
    for (int d = 0; d < DD; ++d) qp += qraw[d] * P0[d * DD + e];
    float qa = tanhf(expf(log_gain[e]) * qp);
    g_qphi[(b * LL + l) * DD + e] = c0 * qa + c1 * qa * qa;
}

// -------------------------------------------------------------------------
// Scan: one CTA per batch, 256 threads (8 warps), persistent over t=0..511
// smem: S,T,M (128x132 each) + vectors
// Per step:
//   pred = M k_t ; err = pred - x_t ; S = 0.9 S + err k_t^T ; nrm = ||S||_F
//   T = S S^T ; U = T S   (tf32 mma, per-warp 32-row x 64-col tile)
//   M = 0.99 M - (0.015/nrm) S + (0.005/nrm^3) U
//   y_t = M q_t
// -------------------------------------------------------------------------
__global__ __launch_bounds__(256, 1)
void scan_kernel(const float* __restrict__ x,
                 const float* __restrict__ M0,
                 const float* __restrict__ S0) {
    extern __shared__ float sm[];
    float* Ssm = sm;                       // 128*132
    float* Tsm = Ssm + DD * SPITCH;        // 128*132
    float* Msm = Tsm + DD * SPITCH;        // 128*132
    float* sk  = Msm + DD * SPITCH;        // 128
    float* sq  = sk + DD;                  // 128
    float* sx  = sq + DD;                  // 128
    float* esm = sx + DD;                  // 128
    float* red = esm + DD;                 // 256
    float* snp = red + 256;                // 1 (+pad)

    const int tid = threadIdx.x;
    const int b = blockIdx.x;
    const float* kphi = g_kphi + b * LL * DD;
    const float* qphi = g_qphi + b * LL * DD;
    const float* xb = x + b * LL * DD;
    float* yb = g_y + b * LL * DD;

    // init state
    for (int i = tid; i < DD * DD; i += 256) {
        int r = i >> 7, c = i & 127;
        Msm[r * SPITCH + c] = M0[i];
        Ssm[r * SPITCH + c] = S0[i];
    }
    float rk = 0.f, rq = 0.f, rx = 0.f;
    if (tid < DD) { rk = kphi[tid]; rq = qphi[tid]; rx = xb[tid]; }
    __syncthreads();

    const int lane = tid & 31, warp = tid >> 5;
    const int g = lane >> 2, t4 = lane & 3;
    const int mS = (warp & 3) * 32;        // 32-row strip
    const int nB = (warp >> 2) * 64;       // 64-col half
    const int rr = tid >> 1, rh = tid & 1; // matvec mapping: 2 threads per row

    for (int t = 0; t < LL; ++t) {
        // stage this step's vectors
        if (tid < DD) { sk[tid] = rk; sq[tid] = rq; sx[tid] = rx; }
        __syncthreads();
        // prefetch next step's vectors (latency hidden across the step)
        if (tid < DD) {
            int tn = (t + 1 < LL) ? t + 1 : t;
            rk = kphi[tn * DD + tid];
            rq = qphi[tn * DD + tid];
            rx = xb[tn * DD + tid];
        }

        // pred = M k_t ; err = pred - x_t
        {
            float s = 0.f;
            const float* Mr = &Msm[rr * SPITCH + rh * 64];
            const float* kr = &sk[rh * 64];
#pragma unroll 16
            for (int j = 0; j < 64; ++j) s += Mr[j] * kr[j];
            s += __shfl_xor_sync(0xffffffffu, s, 1);
            if (rh == 0) esm[rr] = s - sx[rr];
        }
        __syncthreads();

        // S = 0.9 S + err k^T ; partial sumsq
        float ps = 0.f;
        for (int i = tid; i < 4096; i += 256) {
            int r = i >> 5, c4 = (i & 31) << 2;
            float4 s4 = *(const float4*)&Ssm[r * SPITCH + c4];
            float4 k4 = *(const float4*)&sk[c4];
            float er = esm[r];
            s4.x = 0.9f * s4.x + er * k4.x;
            s4.y = 0.9f * s4.y + er * k4.y;
            s4.z = 0.9f * s4.z + er * k4.z;
            s4.w = 0.9f * s4.w + er * k4.w;
            *(float4*)&Ssm[r * SPITCH + c4] = s4;
            ps += s4.x * s4.x + s4.y * s4.y + s4.z * s4.z + s4.w * s4.w;
        }
        red[tid] = ps;
        __syncthreads();
        if (tid < 32) {
            float v = 0.f;
#pragma unroll
            for (int j = 0; j < 8; ++j) v += red[tid + j * 32];
#pragma unroll
            for (int o = 16; o; o >>= 1) v += __shfl_xor_sync(0xffffffffu, v, o);
            if (tid == 0) *snp = v;
        }
        __syncthreads();
        const float sumsq = *snp;

        // ---- MM1: T = S S^T  (strip [mS,mS+32) x cols [nB,nB+64)) ----
        float acc[16][4];
#pragma unroll
        for (int i = 0; i < 16; ++i) { acc[i][0] = 0.f; acc[i][1] = 0.f; acc[i][2] = 0.f; acc[i][3] = 0.f; }
        for (int kk = 0; kk < 16; ++kk) {
            const int k0 = kk * 8;
            unsigned A[2][4];
#pragma unroll
            for (int mt = 0; mt < 2; ++mt) {
                const float* ar = &Ssm[(mS + mt * 16 + g) * SPITCH + k0 + t4];
                A[mt][0] = __float_as_uint(ar[0]);
                A[mt][2] = __float_as_uint(ar[4]);
                A[mt][1] = __float_as_uint(ar[8 * SPITCH]);
                A[mt][3] = __float_as_uint(ar[8 * SPITCH + 4]);
            }
#pragma unroll
            for (int nn = 0; nn < 8; ++nn) {
                const float* br = &Ssm[(nB + nn * 8 + g) * SPITCH + k0 + t4];
                unsigned b0 = __float_as_uint(br[0]);
                unsigned b1 = __float_as_uint(br[4]);
                mma8(acc[nn],     A[0][0], A[0][1], A[0][2], A[0][3], b0, b1);
                mma8(acc[8 + nn], A[1][0], A[1][1], A[1][2], A[1][3], b0, b1);
            }
        }
        // write T strip
#pragma unroll
        for (int mt = 0; mt < 2; ++mt)
#pragma unroll
            for (int nn = 0; nn < 8; ++nn) {
                float* tp = &Tsm[(mS + mt * 16 + g) * SPITCH + nB + nn * 8 + 2 * t4];
                tp[0] = acc[mt * 8 + nn][0];
                tp[1] = acc[mt * 8 + nn][1];
                tp[8 * SPITCH] = acc[mt * 8 + nn][2];
                tp[8 * SPITCH + 1] = acc[mt * 8 + nn][3];
            }
        __syncthreads();

        // ---- MM2: U = T S ----
#pragma unroll
        for (int i = 0; i < 16; ++i) { acc[i][0] = 0.f; acc[i][1] = 0.f; acc[i][2] = 0.f; acc[i][3] = 0.f; }
        for (int kk = 0; kk < 16; ++kk) {
            const int k0 = kk * 8;
            unsigned A[2][4];
#pragma unroll
            for (int mt = 0; mt < 2; ++mt) {
                const float* ar = &Tsm[(mS + mt * 16 + g) * SPITCH + k0 + t4];
                A[mt][0] = __float_as_uint(ar[0]);
                A[mt][2] = __float_as_uint(ar[4]);
                A[mt][1] = __float_as_uint(ar[8 * SPITCH]);
                A[mt][3] = __float_as_uint(ar[8 * SPITCH + 4]);
            }
#pragma unroll
            for (int nn = 0; nn < 8; ++nn) {
                const float* bp = &Ssm[(k0 + t4) * SPITCH + nB + nn * 8 + g];
                unsigned b0 = __float_as_uint(bp[0]);
                unsigned b1 = __float_as_uint(bp[4 * SPITCH]);
                mma8(acc[nn],     A[0][0], A[0][1], A[0][2], A[0][3], b0, b1);
                mma8(acc[8 + nn], A[1][0], A[1][1], A[1][2], A[1][3], b0, b1);
            }
        }

        // M = 0.99 M - (0.015/nrm) S + (0.005/nrm^3) U
        {
            const float inv = 1.0f / (sqrtf(sumsq) + 1e-6f);
            const float cS = 0.015f * inv;
            const float cU = 0.005f * inv * inv * inv;
#pragma unroll
            for (int mt = 0; mt < 2; ++mt)
#pragma unroll
                for (int nn = 0; nn < 8; ++nn) {
                    const int i0 = (mS + mt * 16 + g) * SPITCH + nB + nn * 8 + 2 * t4;
                    const int i8 = i0 + 8 * SPITCH;
                    Msm[i0]     = 0.99f * Msm[i0]     - cS * Ssm[i0]     + cU * acc[mt * 8 + nn][0];
                    Msm[i0 + 1] = 0.99f * Msm[i0 + 1] - cS * Ssm[i0 + 1] + cU * acc[mt * 8 + nn][1];
                    Msm[i8]     = 0.99f * Msm[i8]     - cS * Ssm[i8]     + cU * acc[mt * 8 + nn][2];
                    Msm[i8 + 1] = 0.99f * Msm[i8 + 1] - cS * Ssm[i8 + 1] + cU * acc[mt * 8 + nn][3];
                }
        }
        __syncthreads();

        // y_t = M q_t
        {
            float s = 0.f;
            const float* Mr = &Msm[rr * SPITCH + rh * 64];
            const float* qr = &sq[rh * 64];
#pragma unroll 16
            for (int j = 0; j < 64; ++j) s += Mr[j] * qr[j];
            s += __shfl_xor_sync(0xffffffffu, s, 1);
            if (rh == 0) yb[t * DD + rr] = s;
        }
        __syncthreads();
    }
}

// -------------------------------------------------------------------------
// Postpass: out = y @ Wout^T + bout
// -------------------------------------------------------------------------
__global__ void postpass_kernel(const float* __restrict__ Wout,
                                const float* __restrict__ bout,
                                float* __restrict__ out) {
    const int l = blockIdx.x, b = blockIdx.y;
    const int e = threadIdx.x;
    __shared__ float ys[DD];
    ys[e] = g_y[(b * LL + l) * DD + e];
    __syncthreads();
    float s = 0.f;
    const float* wr = Wout + e * DD;
#pragma unroll 8
    for (int d = 0; d < DD; ++d) s += ys[d] * wr[d];
    out[(b * LL + l) * DD + e] = s + bout[e];
}

// -------------------------------------------------------------------------
// Harness entry
// -------------------------------------------------------------------------
extern "C" void kernel_launch(void* const* d_in, const int* in_sizes, int n_in,
                              void* d_out, int out_size) {
    const float* x    = (const float*)d_in[0];
    const float* Wq   = (const float*)d_in[1];
    const float* Wk   = (const float*)d_in[2];
    const float* P0   = (const float*)d_in[3];
    const float* M0   = (const float*)d_in[4];
    const float* S0   = (const float*)d_in[5];
    const float* lg   = (const float*)d_in[6];
    const float* cf   = (const float*)d_in[7];
    const float* Wout = (const float*)d_in[8];
    const float* bout = (const float*)d_in[9];
    float* out = (float*)d_out;

    const int SMEM_BYTES = (3 * DD * SPITCH + 4 * DD + 256 + 8) * (int)sizeof(float);
    cudaFuncSetAttribute(scan_kernel, cudaFuncAttributeMaxDynamicSharedMemorySize, SMEM_BYTES);

    prepass_kernel<<<dim3(LL, BB), DD>>>(x, Wq, Wk, P0, lg, cf);
    scan_kernel<<<BB, 256, SMEM_BYTES>>>(x, M0, S0);
    postpass_kernel<<<dim3(LL, BB), DD>>>(Wout, bout, out);
}

// round 2
// speedup vs baseline: 1.0011x; 1.0011x over previous
#include <cuda_runtime.h>
#include <math.h>

// Problem constants
#define BB 16
#define LL 512
#define DD 128
#define SPITCH 132                 // padded row pitch (floats) for bank-conflict-free frags

// Scratch (device globals; no allocation allowed)
__device__ float g_kphi[BB * LL * DD];
__device__ float g_qphi[BB * LL * DD];
__device__ float g_y[BB * LL * DD];

// -------------------------------------------------------------------------
// mma.sync m16n8k8 tf32 (fallback HMMA path on sm_103a)
// -------------------------------------------------------------------------
__device__ __forceinline__ void mma8(float* c,
                                     unsigned a0, unsigned a1, unsigned a2, unsigned a3,
                                     unsigned b0, unsigned b1) {
    asm volatile(
        "mma.sync.aligned.m16n8k8.row.col.f32.tf32.tf32.f32 "
        "{%0,%1,%2,%3},{%4,%5,%6,%7},{%8,%9},{%0,%1,%2,%3};\n"
        : "+f"(c[0]), "+f"(c[1]), "+f"(c[2]), "+f"(c[3])
        : "r"(a0), "r"(a1), "r"(a2), "r"(a3), "r"(b0), "r"(b1));
}

// -------------------------------------------------------------------------
// Prepass: q/k projections + normalize + QKProjection(tanh) + poly features
// grid (L, B), 128 threads; thread e computes output feature e for (b,l)
// -------------------------------------------------------------------------
__global__ void prepass_kernel(const float* __restrict__ x,
                               const float* __restrict__ Wq,
                               const float* __restrict__ Wk,
                               const float* __restrict__ P0,
                               const float* __restrict__ log_gain,
                               const float* __restrict__ coeffs) {
    const int l = blockIdx.x, b = blockIdx.y;
    const int e = threadIdx.x;
    __shared__ float xs[DD];
    __shared__ float qraw[DD];
    __shared__ float red[4];

    const float* xp = x + (b * LL + l) * DD;
    xs[e] = xp[e];
    __syncthreads();

    float qr = 0.f, kr = 0.f;
    const float* wqr = Wq + e * DD;
    const float* wkr = Wk + e * DD;
#pragma unroll 8
    for (int d = 0; d < DD; ++d) {
        float xv = xs[d];
        qr += xv * wqr[d];
        kr += xv * wkr[d];
    }
    qraw[e] = qr;

    // ||k||_2 reduction (deterministic tree)
    float ps = kr * kr;
#pragma unroll
    for (int o = 16; o; o >>= 1) ps += __shfl_xor_sync(0xffffffffu, ps, o);
    if ((e & 31) == 0) red[e >> 5] = ps;
    __syncthreads();
    float nrm = sqrtf(red[0] + red[1] + red[2] + red[3]);
    float kn = kr / fmaxf(nrm, 1e-12f);

    const float c0 = coeffs[0], c1 = coeffs[1];
    g_kphi[(b * LL + l) * DD + e] = c0 * kn + c1 * kn * kn;

    // q_aligned = tanh(gain * (q @ P0))
    float qp = 0.f;
#pragma unroll 8
    for (int d = 0; d < DD; ++d) qp += qraw[d] * P0[d * DD + e];
    float qa = tanhf(expf(log_gain[e]) * qp);
    g_qphi[(b * LL + l) * DD + e] = c0 * qa + c1 * qa * qa;
}

// -------------------------------------------------------------------------
// Scan: one CTA per batch, 256 threads (8 warps), persistent over t=0..511
// smem: S,T,M (128x132 each) + vectors
// Per step:
//   pred = M k_t ; err = pred - x_t ; S = 0.9 S + err k_t^T ; nrm = ||S||_F
//   T = S S^T ; U = T S   (tf32 mma, per-warp 32-row x 64-col tile)
//   M = 0.99 M - (0.015/nrm) S + (0.005/nrm^3) U
//   y_t = M q_t
// -------------------------------------------------------------------------
__global__ __launch_bounds__(256, 1)
void scan_kernel(const float* __restrict__ x,
                 const float* __restrict__ M0,
                 const float* __restrict__ S0) {
    extern __shared__ float sm[];
    float* Ssm = sm;                       // 128*132
    float* Tsm = Ssm + DD * SPITCH;        // 128*132
    float* Msm = Tsm + DD * SPITCH;        // 128*132
    float* sk  = Msm + DD * SPITCH;        // 128
    float* sq  = sk + DD;                  // 128
    float* sx  = sq + DD;                  // 128
    float* esm = sx + DD;                  // 128
    float* red = esm + DD;                 // 256
    float* snp = red + 256;                // 1 (+pad)

    const int tid = threadIdx.x;
    const int b = blockIdx.x;
    const float* kphi = g_kphi + b * LL * DD;
    const float* qphi = g_qphi + b * LL * DD;
    const float* xb = x + b * LL * DD;
    float* yb = g_y + b * LL * DD;

    // init state
    for (int i = tid; i < DD * DD; i += 256) {
        int r = i >> 7, c = i & 127;
        Msm[r * SPITCH + c] = M0[i];
        Ssm[r * SPITCH + c] = S0[i];
    }
    float rk = 0.f, rq = 0.f, rx = 0.f;
    if (tid < DD) { rk = kphi[tid]; rq = qphi[tid]; rx = xb[tid]; }
    __syncthreads();

    const int lane = tid & 31, warp = tid >> 5;
    const int g = lane >> 2, t4 = lane & 3;
    const int mS = (warp & 3) * 32;        // 32-row strip
    const int nB = (warp >> 2) * 64;       // 64-col half
    const int rr = tid >> 1, rh = tid & 1; // matvec mapping: 2 threads per row

    for (int t = 0; t < LL; ++t) {
        // stage this step's vectors
        if (tid < DD) { sk[tid] = rk; sq[tid] = rq; sx[tid] = rx; }
        __syncthreads();
        // prefetch next step's vectors (latency hidden across the step)
        if (tid < DD) {
            int tn = (t + 1 < LL) ? t + 1 : t;
            rk = kphi[tn * DD + tid];
            rq = qphi[tn * DD + tid];
            rx = xb[tn * DD + tid];
        }

        // pred = M k_t ; err = pred - x_t
        {
            float s = 0.f;
            const float* Mr = &Msm[rr * SPITCH + rh * 64];
            const float* kr = &sk[rh * 64];
#pragma unroll 16
            for (int j = 0; j < 64; ++j) s += Mr[j] * kr[j];
            s += __shfl_xor_sync(0xffffffffu, s, 1);
            if (rh == 0) esm[rr] = s - sx[rr];
        }
        __syncthreads();

        // S = 0.9 S + err k^T ; partial sumsq
        float ps = 0.f;
        for (int i = tid; i < 4096; i += 256) {
            int r = i >> 5, c4 = (i & 31) << 2;
            float4 s4 = *(const float4*)&Ssm[r * SPITCH + c4];
            float4 k4 = *(const float4*)&sk[c4];
            float er = esm[r];
            s4.x = 0.9f * s4.x + er * k4.x;
            s4.y = 0.9f * s4.y + er * k4.y;
            s4.z = 0.9f * s4.z + er * k4.z;
            s4.w = 0.9f * s4.w + er * k4.w;
            *(float4*)&Ssm[r * SPITCH + c4] = s4;
            ps += s4.x * s4.x + s4.y * s4.y + s4.z * s4.z + s4.w * s4.w;
        }
        red[tid] = ps;
        __syncthreads();
        if (tid < 32) {
            float v = 0.f;
#pragma unroll
            for (int j = 0; j < 8; ++j) v += red[tid + j * 32];
#pragma unroll
            for (int o = 16; o; o >>= 1) v += __shfl_xor_sync(0xffffffffu, v, o);
            if (tid == 0) *snp = v;
        }
        __syncthreads();
        const float sumsq = *snp;

        // ---- MM1: T = S S^T  (strip [mS,mS+32) x cols [nB,nB+64)) ----
        float acc[16][4];
#pragma unroll
        for (int i = 0; i < 16; ++i) { acc[i][0] = 0.f; acc[i][1] = 0.f; acc[i][2] = 0.f; acc[i][3] = 0.f; }
        for (int kk = 0; kk < 16; ++kk) {
            const int k0 = kk * 8;
            unsigned A[2][4];
#pragma unroll
            for (int mt = 0; mt < 2; ++mt) {
                const float* ar = &Ssm[(mS + mt * 16 + g) * SPITCH + k0 + t4];
                A[mt][0] = __float_as_uint(ar[0]);
                A[mt][2] = __float_as_uint(ar[4]);
                A[mt][1] = __float_as_uint(ar[8 * SPITCH]);
                A[mt][3] = __float_as_uint(ar[8 * SPITCH + 4]);
            }
#pragma unroll
            for (int nn = 0; nn < 8; ++nn) {
                const float* br = &Ssm[(nB + nn * 8 + g) * SPITCH + k0 + t4];
                unsigned b0 = __float_as_uint(br[0]);
                unsigned b1 = __float_as_uint(br[4]);
                mma8(acc[nn],     A[0][0], A[0][1], A[0][2], A[0][3], b0, b1);
                mma8(acc[8 + nn], A[1][0], A[1][1], A[1][2], A[1][3], b0, b1);
            }
        }
        // write T strip
#pragma unroll
        for (int mt = 0; mt < 2; ++mt)
#pragma unroll
            for (int nn = 0; nn < 8; ++nn) {
                float* tp = &Tsm[(mS + mt * 16 + g) * SPITCH + nB + nn * 8 + 2 * t4];
                tp[0] = acc[mt * 8 + nn][0];
                tp[1] = acc[mt * 8 + nn][1];
                tp[8 * SPITCH] = acc[mt * 8 + nn][2];
                tp[8 * SPITCH + 1] = acc[mt * 8 + nn][3];
            }
        __syncthreads();

        // ---- MM2: U = T S ----
#pragma unroll
        for (int i = 0; i < 16; ++i) { acc[i][0] = 0.f; acc[i][1] = 0.f; acc[i][2] = 0.f; acc[i][3] = 0.f; }
        for (int kk = 0; kk < 16; ++kk) {
            const int k0 = kk * 8;
            unsigned A[2][4];
#pragma unroll
            for (int mt = 0; mt < 2; ++mt) {
                const float* ar = &Tsm[(mS + mt * 16 + g) * SPITCH + k0 + t4];
                A[mt][0] = __float_as_uint(ar[0]);
                A[mt][2] = __float_as_uint(ar[4]);
                A[mt][1] = __float_as_uint(ar[8 * SPITCH]);
                A[mt][3] = __float_as_uint(ar[8 * SPITCH + 4]);
            }
#pragma unroll
            for (int nn = 0; nn < 8; ++nn) {
                const float* bp = &Ssm[(k0 + t4) * SPITCH + nB + nn * 8 + g];
                unsigned b0 = __float_as_uint(bp[0]);
                unsigned b1 = __float_as_uint(bp[4 * SPITCH]);
                mma8(acc[nn],     A[0][0], A[0][1], A[0][2], A[0][3], b0, b1);
                mma8(acc[8 + nn], A[1][0], A[1][1], A[1][2], A[1][3], b0, b1);
            }
        }

        // M = 0.99 M - (0.015/nrm) S + (0.005/nrm^3) U
        {
            const float inv = 1.0f / (sqrtf(sumsq) + 1e-6f);
            const float cS = 0.015f * inv;
            const float cU = 0.005f * inv * inv * inv;
#pragma unroll
            for (int mt = 0; mt < 2; ++mt)
#pragma unroll
                for (int nn = 0; nn < 8; ++nn) {
                    const int i0 = (mS + mt * 16 + g) * SPITCH + nB + nn * 8 + 2 * t4;
                    const int i8 = i0 + 8 * SPITCH;
                    Msm[i0]     = 0.99f * Msm[i0]     - cS * Ssm[i0]     + cU * acc[mt * 8 + nn][0];
                    Msm[i0 + 1] = 0.99f * Msm[i0 + 1] - cS * Ssm[i0 + 1] + cU * acc[mt * 8 + nn][1];
                    Msm[i8]     = 0.99f * Msm[i8]     - cS * Ssm[i8]     + cU * acc[mt * 8 + nn][2];
                    Msm[i8 + 1] = 0.99f * Msm[i8 + 1] - cS * Ssm[i8 + 1] + cU * acc[mt * 8 + nn][3];
                }
        }
        __syncthreads();

        // y_t = M q_t
        {
            float s = 0.f;
            const float* Mr = &Msm[rr * SPITCH + rh * 64];
            const float* qr = &sq[rh * 64];
#pragma unroll 16
            for (int j = 0; j < 64; ++j) s += Mr[j] * qr[j];
            s += __shfl_xor_sync(0xffffffffu, s, 1);
            if (rh == 0) yb[t * DD + rr] = s;
        }
        __syncthreads();
    }
}

// -------------------------------------------------------------------------
// Postpass: out = y @ Wout^T + bout
// -------------------------------------------------------------------------
__global__ void postpass_kernel(const float* __restrict__ Wout,
                                const float* __restrict__ bout,
                                float* __restrict__ out) {
    const int l = blockIdx.x, b = blockIdx.y;
    const int e = threadIdx.x;
    __shared__ float ys[DD];
    ys[e] = g_y[(b * LL + l) * DD + e];
    __syncthreads();
    float s = 0.f;
    const float* wr = Wout + e * DD;
#pragma unroll 8
    for (int d = 0; d < DD; ++d) s += ys[d] * wr[d];
    out[(b * LL + l) * DD + e] = s + bout[e];
}

// -------------------------------------------------------------------------
// Harness entry
// -------------------------------------------------------------------------
extern "C" void kernel_launch(void* const* d_in, const int* in_sizes, int n_in,
                              void* d_out, int out_size) {
    const float* x    = (const float*)d_in[0];
    const float* Wq   = (const float*)d_in[1];
    const float* Wk   = (const float*)d_in[2];
    const float* P0   = (const float*)d_in[3];
    const float* M0   = (const float*)d_in[4];
    const float* S0   = (const float*)d_in[5];
    const float* lg   = (const float*)d_in[6];
    const float* cf   = (const float*)d_in[7];
    const float* Wout = (const float*)d_in[8];
    const float* bout = (const float*)d_in[9];
    float* out = (float*)d_out;

    const int SMEM_BYTES = (3 * DD * SPITCH + 4 * DD + 256 + 8) * (int)sizeof(float);
    cudaFuncSetAttribute(scan_kernel, cudaFuncAttributeMaxDynamicSharedMemorySize, SMEM_BYTES);

    prepass_kernel<<<dim3(LL, BB), DD>>>(x, Wq, Wk, P0, lg, cf);
    scan_kernel<<<BB, 256, SMEM_BYTES>>>(x, M0, S0);
    postpass_kernel<<<dim3(LL, BB), DD>>>(Wout, bout, out);
}

// round 4
// speedup vs baseline: 2.3658x; 2.3632x over previous
#include <cuda_runtime.h>
#include <math.h>
#include <stdint.h>

#define BB 16
#define LL 512
#define DD 128
#define EPSN 1e-12f
#define TL 16
#define SP 132                      // padded smem pitch (floats)

// Scratch (device globals; no allocation allowed)
__device__ float g_kphi[BB * LL * DD];
__device__ float g_qphi[BB * LL * DD];
__device__ float g_y[BB * LL * DD];
__device__ float g_WqT[DD * DD];
__device__ float g_WkT[DD * DD];
__device__ float g_WoT[DD * DD];

// ---------------- PTX helpers ----------------
__device__ __forceinline__ uint32_t smem_u32(const void* p) {
    uint32_t a;
    asm("{ .reg .u64 t; cvta.to.shared.u64 t, %1; cvt.u32.u64 %0, t; }" : "=r"(a) : "l"(p));
    return a;
}
__device__ __forceinline__ uint32_t cluster_rank() {
    uint32_t r;
    asm("mov.u32 %0, %%cluster_ctarank;" : "=r"(r));
    return r;
}
#define CARRIVE() asm volatile("barrier.cluster.arrive.aligned;" ::: "memory")
#define CWAIT()   asm volatile("barrier.cluster.wait.aligned;" ::: "memory")

__device__ __forceinline__ void peer_store_f32(uint32_t laddr, uint32_t prank, float v) {
    uint32_t paddr;
    asm volatile("mapa.shared::cluster.u32 %0, %1, %2;" : "=r"(paddr) : "r"(laddr), "r"(prank));
    asm volatile("st.shared::cluster.b32 [%0], %1;" :: "r"(paddr), "r"(__float_as_uint(v)) : "memory");
}

__device__ __forceinline__ void mma8(float* c,
                                     unsigned a0, unsigned a1, unsigned a2, unsigned a3,
                                     unsigned b0, unsigned b1) {
    asm volatile(
        "mma.sync.aligned.m16n8k8.row.col.f32.tf32.tf32.f32 "
        "{%0,%1,%2,%3},{%4,%5,%6,%7},{%8,%9},{%0,%1,%2,%3};\n"
        : "+f"(c[0]), "+f"(c[1]), "+f"(c[2]), "+f"(c[3])
        : "r"(a0), "r"(a1), "r"(a2), "r"(a3), "r"(b0), "r"(b1));
}

// ---------------- transpose Wq/Wk/Wout ----------------
__global__ void transpose_k(const float* __restrict__ Wq,
                            const float* __restrict__ Wk,
                            const float* __restrict__ Wo) {
    __shared__ float tb[32][33];
    const float* src = blockIdx.z == 0 ? Wq : (blockIdx.z == 1 ? Wk : Wo);
    float* dst = blockIdx.z == 0 ? g_WqT : (blockIdx.z == 1 ? g_WkT : g_WoT);
    int tx = threadIdx.x, ty = threadIdx.y;
    int bx = blockIdx.x * 32, by = blockIdx.y * 32;
#pragma unroll
    for (int j = 0; j < 32; j += 8) tb[ty + j][tx] = src[(by + ty + j) * DD + bx + tx];
    __syncthreads();
#pragma unroll
    for (int j = 0; j < 32; j += 8) dst[(bx + ty + j) * DD + by + tx] = tb[tx][ty + j];
}

// ---------------- prepass (coalesced, 16 timesteps/block) ----------------
__global__ __launch_bounds__(DD)
void prepass_kernel(const float* __restrict__ x,
                    const float* __restrict__ P0,
                    const float* __restrict__ log_gain,
                    const float* __restrict__ coeffs) {
    const int b = blockIdx.y, l0 = blockIdx.x * TL;
    const int e = threadIdx.x;
    __shared__ float xs[TL][DD];
    __shared__ float qs[TL][DD];
    __shared__ float rn[TL];

    const float* xp = x + (b * LL + l0) * DD;
#pragma unroll
    for (int tt = 0; tt < TL; ++tt) xs[tt][e] = xp[tt * DD + e];
    __syncthreads();

    float qa[TL], ka[TL];
#pragma unroll
    for (int tt = 0; tt < TL; ++tt) { qa[tt] = 0.f; ka[tt] = 0.f; }
    for (int d = 0; d < DD; ++d) {
        float wq = g_WqT[d * DD + e], wk = g_WkT[d * DD + e];
#pragma unroll
        for (int tt = 0; tt < TL; ++tt) {
            float xv = xs[tt][d];
            qa[tt] += xv * wq;
            ka[tt] += xv * wk;
        }
    }
#pragma unroll
    for (int tt = 0; tt < TL; ++tt) qs[tt][e] = qa[tt];
    __syncthreads();
#pragma unroll
    for (int tt = 0; tt < TL; ++tt) xs[tt][e] = ka[tt] * ka[tt];
    __syncthreads();
    {
        const int w = e >> 5, l = e & 31;
#pragma unroll
        for (int i = 0; i < 4; ++i) {
            int tt = w * 4 + i;
            float v = xs[tt][l] + xs[tt][l + 32] + xs[tt][l + 64] + xs[tt][l + 96];
#pragma unroll
            for (int o = 16; o; o >>= 1) v += __shfl_xor_sync(0xffffffffu, v, o);
            if (l == 0) rn[tt] = 1.0f / fmaxf(sqrtf(v), EPSN);
        }
    }
    __syncthreads();

    float qp[TL];
#pragma unroll
    for (int tt = 0; tt < TL; ++tt) qp[tt] = 0.f;
    for (int d = 0; d < DD; ++d) {
        float p = P0[d * DD + e];
#pragma unroll
        for (int tt = 0; tt < TL; ++tt) qp[tt] += qs[tt][d] * p;
    }
    const float gain = expf(log_gain[e]);
    const float c0 = coeffs[0], c1 = coeffs[1];
#pragma unroll
    for (int tt = 0; tt < TL; ++tt) {
        float kn = ka[tt] * rn[tt];
        g_kphi[(b * LL + l0 + tt) * DD + e] = c0 * kn + c1 * kn * kn;
        float qv = tanhf(gain * qp[tt]);
        g_qphi[(b * LL + l0 + tt) * DD + e] = c0 * qv + c1 * qv * qv;
    }
}

// ---------------- postpass ----------------
__global__ __launch_bounds__(DD)
void postpass_kernel(const float* __restrict__ bout, float* __restrict__ out) {
    const int b = blockIdx.y, l0 = blockIdx.x * TL;
    const int e = threadIdx.x;
    __shared__ float ys[TL][DD];
#pragma unroll
    for (int tt = 0; tt < TL; ++tt) ys[tt][e] = g_y[(b * LL + l0 + tt) * DD + e];
    __syncthreads();
    float acc[TL];
#pragma unroll
    for (int tt = 0; tt < TL; ++tt) acc[tt] = 0.f;
    for (int d = 0; d < DD; ++d) {
        float w = g_WoT[d * DD + e];
#pragma unroll
        for (int tt = 0; tt < TL; ++tt) acc[tt] += ys[tt][d] * w;
    }
    const float bo = bout[e];
#pragma unroll
    for (int tt = 0; tt < TL; ++tt) out[(b * LL + l0 + tt) * DD + e] = acc[tt] + bo;
}

// ---------------- scan: 2-CTA cluster per batch ----------------
// smem (floats): S[128*132] | T[64*132] | skb[2*128] | sq[128] | sxn[128] |
//                esm[2*128] | yp[64*17] | pk[64*17] | red[8]
#define OFF_T   16896
#define OFF_SKB 25344
#define OFF_SQ  25600
#define OFF_SXN 25728
#define OFF_ESM 25856
#define OFF_YP  26112
#define OFF_PK  27200
#define OFF_RED 28288
#define SCAN_FLOATS 28304
#define SCAN_SMEM (SCAN_FLOATS * 4)

__global__ __launch_bounds__(256, 1)
void scan_kernel(const float* __restrict__ x,
                 const float* __restrict__ M0,
                 const float* __restrict__ S0) {
    extern __shared__ float sm[];
    float* Ssm = sm;
    float* Tsm = sm + OFF_T;
    float* skb = sm + OFF_SKB;
    float* sq  = sm + OFF_SQ;
    float* sxn = sm + OFF_SXN;
    float* esm = sm + OFF_ESM;
    float* yp  = sm + OFF_YP;
    float* pk  = sm + OFF_PK;
    float* red = sm + OFF_RED;

    const int tid = threadIdx.x;
    const int w = tid >> 5, l = tid & 31;
    const int g = l >> 2, t4 = l & 3;
    const uint32_t rk = cluster_rank();
    const uint32_t prank = rk ^ 1u;
    const int batch = blockIdx.x >> 1;
    const int mS = (w & 1) * 32;        // local 32-row strip within this CTA's 64 rows
    const int nB = (w >> 1) * 32;       // 32-col group
    const int rbase = (int)rk * 64;     // global row offset owned by this CTA
    const int pcol = (w >> 1) * 4 + t4; // partial-sum column

    const float* kphi = g_kphi + batch * LL * DD;
    const float* qphi = g_qphi + batch * LL * DD;
    const float* xb = x + batch * LL * DD;
    float* yb = g_y + batch * LL * DD;

    // init full S (both CTAs keep a full copy)
    for (int i = tid; i < DD * DD; i += 256) {
        int r = i >> 7, c = i & 127;
        Ssm[r * SP + c] = S0[i];
    }
    // M fragments for owned 64 rows
    float m[2][4][4];
#pragma unroll
    for (int mt = 0; mt < 2; ++mt)
#pragma unroll
        for (int nn = 0; nn < 4; ++nn) {
            int r0 = rbase + mS + mt * 16 + g;
            int c = nB + nn * 8 + 2 * t4;
            m[mt][nn][0] = M0[r0 * DD + c];
            m[mt][nn][1] = M0[r0 * DD + c + 1];
            m[mt][nn][2] = M0[(r0 + 8) * DD + c];
            m[mt][nn][3] = M0[(r0 + 8) * DD + c + 1];
        }
    if (tid < DD) { skb[tid] = kphi[tid]; sxn[tid] = xb[tid]; }
    __syncthreads();

    // pred_0 partials = M0 * k_0 (owned rows)
    {
        float pv[2][2] = {{0.f, 0.f}, {0.f, 0.f}};
#pragma unroll
        for (int nn = 0; nn < 4; ++nn) {
            int c = nB + nn * 8 + 2 * t4;
            float2 k2 = *(const float2*)&skb[c];
#pragma unroll
            for (int mt = 0; mt < 2; ++mt) {
                pv[mt][0] += m[mt][nn][0] * k2.x + m[mt][nn][1] * k2.y;
                pv[mt][1] += m[mt][nn][2] * k2.x + m[mt][nn][3] * k2.y;
            }
        }
        pk[(mS + g) * 17 + pcol] = pv[0][0];
        pk[(mS + g + 8) * 17 + pcol] = pv[0][1];
        pk[(mS + 16 + g) * 17 + pcol] = pv[1][0];
        pk[(mS + 24 + g) * 17 + pcol] = pv[1][1];
    }
    __syncthreads();
    if (tid >= 64 && tid < 128) {
        int i = tid - 64;
        float s = 0.f;
#pragma unroll
        for (int j = 0; j < 16; ++j) s += pk[i * 17 + j];
        float e = s - sxn[rbase + i];
        esm[rbase + i] = e;
        peer_store_f32(smem_u32(&esm[rbase + i]), prank, e);
    }
    __syncthreads();
    CARRIVE();

    for (int t = 0; t < LL; ++t) {
        const int buf = t & 1;
        // stage q_t, k_{t+1}, x_{t+1}
        if (tid < DD) {
            sq[tid] = qphi[t * DD + tid];
            int tn = (t + 1 < LL) ? t + 1 : t;
            skb[(buf ^ 1) * DD + tid] = kphi[tn * DD + tid];
            sxn[tid] = xb[tn * DD + tid];
        }
        CWAIT();   // err[buf] fully exchanged

        // S = 0.9 S + err k^T ; sumsq
        float ps = 0.f;
#pragma unroll
        for (int it = 0; it < 16; ++it) {
            int idx = tid + it * 256;
            int rr = idx >> 5, c4 = (idx & 31) << 2;
            float4* sp = (float4*)&Ssm[rr * SP + c4];
            float4 s4 = *sp;
            float er = esm[buf * DD + rr];
            float4 k4 = *(const float4*)&skb[buf * DD + c4];
            s4.x = 0.9f * s4.x + er * k4.x;
            s4.y = 0.9f * s4.y + er * k4.y;
            s4.z = 0.9f * s4.z + er * k4.z;
            s4.w = 0.9f * s4.w + er * k4.w;
            *sp = s4;
            ps += s4.x * s4.x + s4.y * s4.y + s4.z * s4.z + s4.w * s4.w;
        }
#pragma unroll
        for (int o = 16; o; o >>= 1) ps += __shfl_xor_sync(0xffffffffu, ps, o);
        if (l == 0) red[w] = ps;
        __syncthreads();
        float sumsq = 0.f;
#pragma unroll
        for (int j = 0; j < 8; ++j) sumsq += red[j];

        // MM1: T strip = S[owned rows] * S^T  (cols nB..nB+32)
        float acc[2][4][4];
#pragma unroll
        for (int mt = 0; mt < 2; ++mt)
#pragma unroll
            for (int nn = 0; nn < 4; ++nn) {
                acc[mt][nn][0] = 0.f; acc[mt][nn][1] = 0.f;
                acc[mt][nn][2] = 0.f; acc[mt][nn][3] = 0.f;
            }
        for (int kk = 0; kk < 16; ++kk) {
            const int k0 = kk * 8;
            unsigned A[2][4];
#pragma unroll
            for (int mt = 0; mt < 2; ++mt) {
                const float* ar = &Ssm[(rbase + mS + mt * 16 + g) * SP + k0 + t4];
                A[mt][0] = __float_as_uint(ar[0]);
                A[mt][2] = __float_as_uint(ar[4]);
                A[mt][1] = __float_as_uint(ar[8 * SP]);
                A[mt][3] = __float_as_uint(ar[8 * SP + 4]);
            }
#pragma unroll
            for (int nn = 0; nn < 4; ++nn) {
                const float* br = &Ssm[(nB + nn * 8 + g) * SP + k0 + t4];
                unsigned b0 = __float_as_uint(br[0]);
                unsigned b1 = __float_as_uint(br[4]);
                mma8(acc[0][nn], A[0][0], A[0][1], A[0][2], A[0][3], b0, b1);
                mma8(acc[1][nn], A[1][0], A[1][1], A[1][2], A[1][3], b0, b1);
            }
        }
        // write local T strip (64 x 128)
#pragma unroll
        for (int mt = 0; mt < 2; ++mt)
#pragma unroll
            for (int nn = 0; nn < 4; ++nn) {
                float* tp = &Tsm[(mS + mt * 16 + g) * SP + nB + nn * 8 + 2 * t4];
                tp[0] = acc[mt][nn][0];
                tp[1] = acc[mt][nn][1];
                tp[8 * SP] = acc[mt][nn][2];
                tp[8 * SP + 1] = acc[mt][nn][3];
            }
        __syncthreads();

        // MM2: U strip = T_strip * S
#pragma unroll
        for (int mt = 0; mt < 2; ++mt)
#pragma unroll
            for (int nn = 0; nn < 4; ++nn) {
                acc[mt][nn][0] = 0.f; acc[mt][nn][1] = 0.f;
                acc[mt][nn][2] = 0.f; acc[mt][nn][3] = 0.f;
            }
        for (int kk = 0; kk < 16; ++kk) {
            const int k0 = kk * 8;
            unsigned A[2][4];
#pragma unroll
            for (int mt = 0; mt < 2; ++mt) {
                const float* ar = &Tsm[(mS + mt * 16 + g) * SP + k0 + t4];
                A[mt][0] = __float_as_uint(ar[0]);
                A[mt][2] = __float_as_uint(ar[4]);
                A[mt][1] = __float_as_uint(ar[8 * SP]);
                A[mt][3] = __float_as_uint(ar[8 * SP + 4]);
            }
#pragma unroll
            for (int nn = 0; nn < 4; ++nn) {
                const float* bp = &Ssm[(k0 + t4) * SP + nB + nn * 8 + g];
                unsigned b0 = __float_as_uint(bp[0]);
                unsigned b1 = __float_as_uint(bp[4 * SP]);
                mma8(acc[0][nn], A[0][0], A[0][1], A[0][2], A[0][3], b0, b1);
                mma8(acc[1][nn], A[1][0], A[1][1], A[1][2], A[1][3], b0, b1);
            }
        }

        // epilogue: M frag update + y_t / pred_{t+1} partials
        {
            const float invn = 1.0f / (sqrtf(sumsq) + 1e-6f);
            const float cS = 0.015f * invn;
            const float cU = 0.005f * invn * invn * invn;
            float yv[2][2] = {{0.f, 0.f}, {0.f, 0.f}};
            float pv[2][2] = {{0.f, 0.f}, {0.f, 0.f}};
#pragma unroll
            for (int nn = 0; nn < 4; ++nn) {
                int c = nB + nn * 8 + 2 * t4;
                float2 q2 = *(const float2*)&sq[c];
                float2 k2 = *(const float2*)&skb[(buf ^ 1) * DD + c];
#pragma unroll
                for (int mt = 0; mt < 2; ++mt) {
                    int r0 = rbase + mS + mt * 16 + g;
                    float2 s0 = *(const float2*)&Ssm[r0 * SP + c];
                    float2 s1 = *(const float2*)&Ssm[(r0 + 8) * SP + c];
                    float m0 = 0.99f * m[mt][nn][0] - cS * s0.x + cU * acc[mt][nn][0];
                    float m1 = 0.99f * m[mt][nn][1] - cS * s0.y + cU * acc[mt][nn][1];
                    float m2 = 0.99f * m[mt][nn][2] - cS * s1.x + cU * acc[mt][nn][2];
                    float m3 = 0.99f * m[mt][nn][3] - cS * s1.y + cU * acc[mt][nn][3];
                    m[mt][nn][0] = m0; m[mt][nn][1] = m1;
                    m[mt][nn][2] = m2; m[mt][nn][3] = m3;
                    yv[mt][0] += m0 * q2.x + m1 * q2.y;
                    yv[mt][1] += m2 * q2.x + m3 * q2.y;
                    pv[mt][0] += m0 * k2.x + m1 * k2.y;
                    pv[mt][1] += m2 * k2.x + m3 * k2.y;
                }
            }
            yp[(mS + g) * 17 + pcol] = yv[0][0];
            yp[(mS + g + 8) * 17 + pcol] = yv[0][1];
            yp[(mS + 16 + g) * 17 + pcol] = yv[1][0];
            yp[(mS + 24 + g) * 17 + pcol] = yv[1][1];
            pk[(mS + g) * 17 + pcol] = pv[0][0];
            pk[(mS + g + 8) * 17 + pcol] = pv[0][1];
            pk[(mS + 16 + g) * 17 + pcol] = pv[1][0];
            pk[(mS + 24 + g) * 17 + pcol] = pv[1][1];
        }
        __syncthreads();

        if (tid < 64) {
            float s = 0.f;
#pragma unroll
            for (int j = 0; j < 16; ++j) s += yp[tid * 17 + j];
            yb[t * DD + rbase + tid] = s;
        } else if (tid < 128 && t + 1 < LL) {
            int i = tid - 64;
            float s = 0.f;
#pragma unroll
            for (int j = 0; j < 16; ++j) s += pk[i * 17 + j];
            float e = s - sxn[rbase + i];
            esm[(buf ^ 1) * DD + rbase + i] = e;
            peer_store_f32(smem_u32(&esm[(buf ^ 1) * DD + rbase + i]), prank, e);
        }
        __syncthreads();
        if (t + 1 < LL) CARRIVE();
    }
}

// ---------------- harness entry ----------------
extern "C" void kernel_launch(void* const* d_in, const int* in_sizes, int n_in,
                              void* d_out, int out_size) {
    const float* x    = (const float*)d_in[0];
    const float* Wq   = (const float*)d_in[1];
    const float* Wk   = (const float*)d_in[2];
    const float* P0   = (const float*)d_in[3];
    const float* M0   = (const float*)d_in[4];
    const float* S0   = (const float*)d_in[5];
    const float* lg   = (const float*)d_in[6];
    const float* cf   = (const float*)d_in[7];
    const float* Wout = (const float*)d_in[8];
    const float* bout = (const float*)d_in[9];
    float* out = (float*)d_out;

    cudaFuncSetAttribute(scan_kernel, cudaFuncAttributeMaxDynamicSharedMemorySize, SCAN_SMEM);

    transpose_k<<<dim3(4, 4, 3), dim3(32, 8)>>>(Wq, Wk, Wout);
    prepass_kernel<<<dim3(LL / TL, BB), DD>>>(x, P0, lg, cf);

    cudaLaunchConfig_t cfg = {};
    cfg.gridDim = dim3(2 * BB, 1, 1);
    cfg.blockDim = dim3(256, 1, 1);
    cfg.dynamicSmemBytes = SCAN_SMEM;
    cfg.stream = 0;
    cudaLaunchAttribute attrs[1];
    attrs[0].id = cudaLaunchAttributeClusterDimension;
    attrs[0].val.clusterDim.x = 2;
    attrs[0].val.clusterDim.y = 1;
    attrs[0].val.clusterDim.z = 1;
    cfg.attrs = attrs;
    cfg.numAttrs = 1;
    cudaLaunchKernelEx(&cfg, scan_kernel, x, M0, S0);

    postpass_kernel<<<dim3(LL / TL, BB), DD>>>(bout, out);
}

// round 5
// speedup vs baseline: 3.2571x; 1.3768x over previous
#include <cuda_runtime.h>
#include <math.h>
#include <stdint.h>

#define BB 16
#define LL 512
#define DD 128
#define EPSN 1e-12f
#define TL 16
#define SP 132                      // padded smem pitch (floats)
#define CS 4                        // cluster size (CTAs per batch)
#define RK 32                       // M rows per CTA

// Scratch (device globals; no allocation allowed)
__device__ float g_kphi[BB * LL * DD];
__device__ float g_qphi[BB * LL * DD];
__device__ float g_y[BB * LL * DD];
__device__ float g_WqT[DD * DD];
__device__ float g_WkT[DD * DD];
__device__ float g_WoT[DD * DD];

// ---------------- PTX helpers ----------------
__device__ __forceinline__ uint32_t smem_u32(const void* p) {
    uint32_t a;
    asm("{ .reg .u64 t; cvta.to.shared.u64 t, %1; cvt.u32.u64 %0, t; }" : "=r"(a) : "l"(p));
    return a;
}
__device__ __forceinline__ uint32_t cluster_rank() {
    uint32_t r;
    asm("mov.u32 %0, %%cluster_ctarank;" : "=r"(r));
    return r;
}
#define CARRIVE() asm volatile("barrier.cluster.arrive.aligned;" ::: "memory")
#define CWAIT()   asm volatile("barrier.cluster.wait.aligned;" ::: "memory")

__device__ __forceinline__ void peer_store_f32(uint32_t laddr, uint32_t prank, float v) {
    uint32_t paddr;
    asm volatile("mapa.shared::cluster.u32 %0, %1, %2;" : "=r"(paddr) : "r"(laddr), "r"(prank));
    asm volatile("st.shared::cluster.b32 [%0], %1;" :: "r"(paddr), "r"(__float_as_uint(v)) : "memory");
}

__device__ __forceinline__ void mma8(float* c,
                                     unsigned a0, unsigned a1, unsigned a2, unsigned a3,
                                     unsigned b0, unsigned b1) {
    asm volatile(
        "mma.sync.aligned.m16n8k8.row.col.f32.tf32.tf32.f32 "
        "{%0,%1,%2,%3},{%4,%5,%6,%7},{%8,%9},{%0,%1,%2,%3};\n"
        : "+f"(c[0]), "+f"(c[1]), "+f"(c[2]), "+f"(c[3])
        : "r"(a0), "r"(a1), "r"(a2), "r"(a3), "r"(b0), "r"(b1));
}

// ---------------- transpose Wq/Wk/Wout ----------------
__global__ void transpose_k(const float* __restrict__ Wq,
                            const float* __restrict__ Wk,
                            const float* __restrict__ Wo) {
    __shared__ float tb[32][33];
    const float* src = blockIdx.z == 0 ? Wq : (blockIdx.z == 1 ? Wk : Wo);
    float* dst = blockIdx.z == 0 ? g_WqT : (blockIdx.z == 1 ? g_WkT : g_WoT);
    int tx = threadIdx.x, ty = threadIdx.y;
    int bx = blockIdx.x * 32, by = blockIdx.y * 32;
#pragma unroll
    for (int j = 0; j < 32; j += 8) tb[ty + j][tx] = src[(by + ty + j) * DD + bx + tx];
    __syncthreads();
#pragma unroll
    for (int j = 0; j < 32; j += 8) dst[(bx + ty + j) * DD + by + tx] = tb[tx][ty + j];
}

// ---------------- prepass (coalesced, 16 timesteps/block) ----------------
__global__ __launch_bounds__(DD)
void prepass_kernel(const float* __restrict__ x,
                    const float* __restrict__ P0,
                    const float* __restrict__ log_gain,
                    const float* __restrict__ coeffs) {
    const int b = blockIdx.y, l0 = blockIdx.x * TL;
    const int e = threadIdx.x;
    __shared__ float xs[TL][DD];
    __shared__ float qs[TL][DD];
    __shared__ float rn[TL];

    const float* xp = x + (b * LL + l0) * DD;
#pragma unroll
    for (int tt = 0; tt < TL; ++tt) xs[tt][e] = xp[tt * DD + e];
    __syncthreads();

    float qa[TL], ka[TL];
#pragma unroll
    for (int tt = 0; tt < TL; ++tt) { qa[tt] = 0.f; ka[tt] = 0.f; }
    for (int d = 0; d < DD; ++d) {
        float wq = g_WqT[d * DD + e], wk = g_WkT[d * DD + e];
#pragma unroll
        for (int tt = 0; tt < TL; ++tt) {
            float xv = xs[tt][d];
            qa[tt] += xv * wq;
            ka[tt] += xv * wk;
        }
    }
#pragma unroll
    for (int tt = 0; tt < TL; ++tt) qs[tt][e] = qa[tt];
    __syncthreads();
#pragma unroll
    for (int tt = 0; tt < TL; ++tt) xs[tt][e] = ka[tt] * ka[tt];
    __syncthreads();
    {
        const int w = e >> 5, l = e & 31;
#pragma unroll
        for (int i = 0; i < 4; ++i) {
            int tt = w * 4 + i;
            float v = xs[tt][l] + xs[tt][l + 32] + xs[tt][l + 64] + xs[tt][l + 96];
#pragma unroll
            for (int o = 16; o; o >>= 1) v += __shfl_xor_sync(0xffffffffu, v, o);
            if (l == 0) rn[tt] = 1.0f / fmaxf(sqrtf(v), EPSN);
        }
    }
    __syncthreads();

    float qp[TL];
#pragma unroll
    for (int tt = 0; tt < TL; ++tt) qp[tt] = 0.f;
    for (int d = 0; d < DD; ++d) {
        float p = P0[d * DD + e];
#pragma unroll
        for (int tt = 0; tt < TL; ++tt) qp[tt] += qs[tt][d] * p;
    }
    const float gain = expf(log_gain[e]);
    const float c0 = coeffs[0], c1 = coeffs[1];
#pragma unroll
    for (int tt = 0; tt < TL; ++tt) {
        float kn = ka[tt] * rn[tt];
        g_kphi[(b * LL + l0 + tt) * DD + e] = c0 * kn + c1 * kn * kn;
        float qv = tanhf(gain * qp[tt]);
        g_qphi[(b * LL + l0 + tt) * DD + e] = c0 * qv + c1 * qv * qv;
    }
}

// ---------------- postpass ----------------
__global__ __launch_bounds__(DD)
void postpass_kernel(const float* __restrict__ bout, float* __restrict__ out) {
    const int b = blockIdx.y, l0 = blockIdx.x * TL;
    const int e = threadIdx.x;
    __shared__ float ys[TL][DD];
#pragma unroll
    for (int tt = 0; tt < TL; ++tt) ys[tt][e] = g_y[(b * LL + l0 + tt) * DD + e];
    __syncthreads();
    float acc[TL];
#pragma unroll
    for (int tt = 0; tt < TL; ++tt) acc[tt] = 0.f;
    for (int d = 0; d < DD; ++d) {
        float w = g_WoT[d * DD + e];
#pragma unroll
        for (int tt = 0; tt < TL; ++tt) acc[tt] += ys[tt][d] * w;
    }
    const float bo = bout[e];
#pragma unroll
    for (int tt = 0; tt < TL; ++tt) out[(b * LL + l0 + tt) * DD + e] = acc[tt] + bo;
}

// ---------------- scan: 4-CTA cluster per batch ----------------
// smem (floats): S[128*132] | T[32*132] | skb[2*128] | sq[128] | sxn[128] |
//                esm[2*128] | yp[32*17] | pk[32*17] | red[8]
#define OFF_T   16896
#define OFF_SKB 21120
#define OFF_SQ  21376
#define OFF_SXN 21504
#define OFF_ESM 21632
#define OFF_YP  21888
#define OFF_PK  22432
#define OFF_RED 22976
#define SCAN_FLOATS 22984
#define SCAN_SMEM (SCAN_FLOATS * 4)

__global__ __launch_bounds__(256, 1)
void scan_kernel(const float* __restrict__ x,
                 const float* __restrict__ M0,
                 const float* __restrict__ S0) {
    extern __shared__ float sm[];
    float* Ssm = sm;
    float* Tsm = sm + OFF_T;
    float* skb = sm + OFF_SKB;
    float* sq  = sm + OFF_SQ;
    float* sxn = sm + OFF_SXN;
    float* esm = sm + OFF_ESM;
    float* yp  = sm + OFF_YP;
    float* pk  = sm + OFF_PK;
    float* red = sm + OFF_RED;

    const int tid = threadIdx.x;
    const int w = tid >> 5, l = tid & 31;
    const int g = l >> 2, t4 = l & 3;
    const uint32_t rk = cluster_rank();
    const int batch = blockIdx.x >> 2;
    const int rbase = (int)rk * RK;       // global row offset owned by this CTA
    const int nB = (w & 3) * 32;          // MMA warp col group (w<4)
    const int pcol = (w & 3) * 4 + t4;

    const float* kphi = g_kphi + batch * LL * DD;
    const float* qphi = g_qphi + batch * LL * DD;
    const float* xb = x + batch * LL * DD;
    float* yb = g_y + batch * LL * DD;

    // init full S (every CTA keeps a full copy)
    for (int i = tid; i < DD * DD; i += 256) {
        int r = i >> 7, c = i & 127;
        Ssm[r * SP + c] = S0[i];
    }
    // M fragments for owned 32 rows (MMA warps only)
    float m[2][4][4];
    if (w < 4) {
#pragma unroll
        for (int mt = 0; mt < 2; ++mt)
#pragma unroll
            for (int nn = 0; nn < 4; ++nn) {
                int r0 = rbase + mt * 16 + g;
                int c = nB + nn * 8 + 2 * t4;
                m[mt][nn][0] = M0[r0 * DD + c];
                m[mt][nn][1] = M0[r0 * DD + c + 1];
                m[mt][nn][2] = M0[(r0 + 8) * DD + c];
                m[mt][nn][3] = M0[(r0 + 8) * DD + c + 1];
            }
    }
    if (tid < DD) { skb[tid] = kphi[tid]; sxn[tid] = xb[tid]; }
    __syncthreads();

    // initial pred partials = M0 * k_0 (owned rows)
    if (w < 4) {
        float pv[2][2] = {{0.f, 0.f}, {0.f, 0.f}};
#pragma unroll
        for (int nn = 0; nn < 4; ++nn) {
            int c = nB + nn * 8 + 2 * t4;
            float2 k2 = *(const float2*)&skb[c];
#pragma unroll
            for (int mt = 0; mt < 2; ++mt) {
                pv[mt][0] += m[mt][nn][0] * k2.x + m[mt][nn][1] * k2.y;
                pv[mt][1] += m[mt][nn][2] * k2.x + m[mt][nn][3] * k2.y;
            }
        }
        pk[g * 17 + pcol] = pv[0][0];
        pk[(g + 8) * 17 + pcol] = pv[0][1];
        pk[(16 + g) * 17 + pcol] = pv[1][0];
        pk[(24 + g) * 17 + pcol] = pv[1][1];
    }
    __syncthreads();
    if (tid >= 160 && tid < 192) {
        int i = tid - 160;
        float s = 0.f;
#pragma unroll
        for (int j = 0; j < 16; ++j) s += pk[i * 17 + j];
        float e = s - sxn[rbase + i];
        uint32_t la = smem_u32(&esm[rbase + i]);
#pragma unroll
        for (uint32_t pr = 0; pr < CS; ++pr) peer_store_f32(la, pr, e);
    }
    CARRIVE();

    for (int t = 0; t < LL; ++t) {
        const int buf = t & 1;
        // stage q_t, k_{t+1}, x_{t+1} (warps 4-7)
        if (tid >= 128) {
            int i = tid - 128;
            sq[i] = qphi[t * DD + i];
            int tn = (t + 1 < LL) ? t + 1 : t;
            skb[(buf ^ 1) * DD + i] = kphi[tn * DD + i];
            sxn[i] = xb[tn * DD + i];
        }
        CWAIT();   // err[buf] fully exchanged (release at arrive / acquire here)

        // S = 0.9 S + err k^T ; sumsq (all 8 warps)
        float ps = 0.f;
#pragma unroll
        for (int it = 0; it < 16; ++it) {
            int idx = tid + it * 256;
            int rr = idx >> 5, c4 = (idx & 31) << 2;
            float4* sp = (float4*)&Ssm[rr * SP + c4];
            float4 s4 = *sp;
            float er = esm[buf * DD + rr];
            float4 k4 = *(const float4*)&skb[buf * DD + c4];
            s4.x = 0.9f * s4.x + er * k4.x;
            s4.y = 0.9f * s4.y + er * k4.y;
            s4.z = 0.9f * s4.z + er * k4.z;
            s4.w = 0.9f * s4.w + er * k4.w;
            *sp = s4;
            ps += s4.x * s4.x + s4.y * s4.y + s4.z * s4.z + s4.w * s4.w;
        }
#pragma unroll
        for (int o = 16; o; o >>= 1) ps += __shfl_xor_sync(0xffffffffu, ps, o);
        if (l == 0) red[w] = ps;
        __syncthreads();

        float acc[2][4][4];
        if (w < 4) {
            // MM1: T strip = S[owned 32 rows] * S^T (cols nB..nB+32)
#pragma unroll
            for (int mt = 0; mt < 2; ++mt)
#pragma unroll
                for (int nn = 0; nn < 4; ++nn) {
                    acc[mt][nn][0] = 0.f; acc[mt][nn][1] = 0.f;
                    acc[mt][nn][2] = 0.f; acc[mt][nn][3] = 0.f;
                }
            for (int kk = 0; kk < 16; ++kk) {
                const int k0 = kk * 8;
                unsigned A[2][4];
#pragma unroll
                for (int mt = 0; mt < 2; ++mt) {
                    const float* ar = &Ssm[(rbase + mt * 16 + g) * SP + k0 + t4];
                    A[mt][0] = __float_as_uint(ar[0]);
                    A[mt][2] = __float_as_uint(ar[4]);
                    A[mt][1] = __float_as_uint(ar[8 * SP]);
                    A[mt][3] = __float_as_uint(ar[8 * SP + 4]);
                }
#pragma unroll
                for (int nn = 0; nn < 4; ++nn) {
                    const float* br = &Ssm[(nB + nn * 8 + g) * SP + k0 + t4];
                    unsigned b0 = __float_as_uint(br[0]);
                    unsigned b1 = __float_as_uint(br[4]);
                    mma8(acc[0][nn], A[0][0], A[0][1], A[0][2], A[0][3], b0, b1);
                    mma8(acc[1][nn], A[1][0], A[1][1], A[1][2], A[1][3], b0, b1);
                }
            }
            // write local T strip (32 x 128)
#pragma unroll
            for (int mt = 0; mt < 2; ++mt)
#pragma unroll
                for (int nn = 0; nn < 4; ++nn) {
                    float* tp = &Tsm[(mt * 16 + g) * SP + nB + nn * 8 + 2 * t4];
                    *(float2*)tp = make_float2(acc[mt][nn][0], acc[mt][nn][1]);
                    *(float2*)(tp + 8 * SP) = make_float2(acc[mt][nn][2], acc[mt][nn][3]);
                }
        }
        __syncthreads();

        if (w < 4) {
            // MM2: U strip = T_strip * S
#pragma unroll
            for (int mt = 0; mt < 2; ++mt)
#pragma unroll
                for (int nn = 0; nn < 4; ++nn) {
                    acc[mt][nn][0] = 0.f; acc[mt][nn][1] = 0.f;
                    acc[mt][nn][2] = 0.f; acc[mt][nn][3] = 0.f;
                }
            for (int kk = 0; kk < 16; ++kk) {
                const int k0 = kk * 8;
                unsigned A[2][4];
#pragma unroll
                for (int mt = 0; mt < 2; ++mt) {
                    const float* ar = &Tsm[(mt * 16 + g) * SP + k0 + t4];
                    A[mt][0] = __float_as_uint(ar[0]);
                    A[mt][2] = __float_as_uint(ar[4]);
                    A[mt][1] = __float_as_uint(ar[8 * SP]);
                    A[mt][3] = __float_as_uint(ar[8 * SP + 4]);
                }
#pragma unroll
                for (int nn = 0; nn < 4; ++nn) {
                    const float* bp = &Ssm[(k0 + t4) * SP + nB + nn * 8 + g];
                    unsigned b0 = __float_as_uint(bp[0]);
                    unsigned b1 = __float_as_uint(bp[4 * SP]);
                    mma8(acc[0][nn], A[0][0], A[0][1], A[0][2], A[0][3], b0, b1);
                    mma8(acc[1][nn], A[1][0], A[1][1], A[1][2], A[1][3], b0, b1);
                }
            }

            // epilogue: M frag update + y_t / pred_{t+1} partials
            float sumsq = 0.f;
#pragma unroll
            for (int j = 0; j < 8; ++j) sumsq += red[j];
            const float invn = 1.0f / (sqrtf(sumsq) + 1e-6f);
            const float cS = 0.015f * invn;
            const float cU = 0.005f * invn * invn * invn;
            float yv[2][2] = {{0.f, 0.f}, {0.f, 0.f}};
            float pv[2][2] = {{0.f, 0.f}, {0.f, 0.f}};
#pragma unroll
            for (int nn = 0; nn < 4; ++nn) {
                int c = nB + nn * 8 + 2 * t4;
                float2 q2 = *(const float2*)&sq[c];
                float2 k2 = *(const float2*)&skb[(buf ^ 1) * DD + c];
#pragma unroll
                for (int mt = 0; mt < 2; ++mt) {
                    int r0 = rbase + mt * 16 + g;
                    float2 s0 = *(const float2*)&Ssm[r0 * SP + c];
                    float2 s1 = *(const float2*)&Ssm[(r0 + 8) * SP + c];
                    float m0 = 0.99f * m[mt][nn][0] - cS * s0.x + cU * acc[mt][nn][0];
                    float m1 = 0.99f * m[mt][nn][1] - cS * s0.y + cU * acc[mt][nn][1];
                    float m2 = 0.99f * m[mt][nn][2] - cS * s1.x + cU * acc[mt][nn][2];
                    float m3 = 0.99f * m[mt][nn][3] - cS * s1.y + cU * acc[mt][nn][3];
                    m[mt][nn][0] = m0; m[mt][nn][1] = m1;
                    m[mt][nn][2] = m2; m[mt][nn][3] = m3;
                    yv[mt][0] += m0 * q2.x + m1 * q2.y;
                    yv[mt][1] += m2 * q2.x + m3 * q2.y;
                    pv[mt][0] += m0 * k2.x + m1 * k2.y;
                    pv[mt][1] += m2 * k2.x + m3 * k2.y;
                }
            }
            yp[g * 17 + pcol] = yv[0][0];
            yp[(g + 8) * 17 + pcol] = yv[0][1];
            yp[(16 + g) * 17 + pcol] = yv[1][0];
            yp[(24 + g) * 17 + pcol] = yv[1][1];
            pk[g * 17 + pcol] = pv[0][0];
            pk[(g + 8) * 17 + pcol] = pv[0][1];
            pk[(16 + g) * 17 + pcol] = pv[1][0];
            pk[(24 + g) * 17 + pcol] = pv[1][1];
        }
        __syncthreads();

        if (tid >= 128 && tid < 160) {
            int i = tid - 128;
            float s = 0.f;
#pragma unroll
            for (int j = 0; j < 16; ++j) s += yp[i * 17 + j];
            yb[t * DD + rbase + i] = s;
        } else if (tid >= 160 && tid < 192 && t + 1 < LL) {
            int i = tid - 160;
            float s = 0.f;
#pragma unroll
            for (int j = 0; j < 16; ++j) s += pk[i * 17 + j];
            float e = s - sxn[rbase + i];
            uint32_t la = smem_u32(&esm[(buf ^ 1) * DD + rbase + i]);
#pragma unroll
            for (uint32_t pr = 0; pr < CS; ++pr) peer_store_f32(la, pr, e);
        }
        if (t + 1 < LL) CARRIVE();
    }
}

// ---------------- harness entry ----------------
extern "C" void kernel_launch(void* const* d_in, const int* in_sizes, int n_in,
                              void* d_out, int out_size) {
    const float* x    = (const float*)d_in[0];
    const float* Wq   = (const float*)d_in[1];
    const float* Wk   = (const float*)d_in[2];
    const float* P0   = (const float*)d_in[3];
    const float* M0   = (const float*)d_in[4];
    const float* S0   = (const float*)d_in[5];
    const float* lg   = (const float*)d_in[6];
    const float* cf   = (const float*)d_in[7];
    const float* Wout = (const float*)d_in[8];
    const float* bout = (const float*)d_in[9];
    float* out = (float*)d_out;

    cudaFuncSetAttribute(scan_kernel, cudaFuncAttributeMaxDynamicSharedMemorySize, SCAN_SMEM);

    transpose_k<<<dim3(4, 4, 3), dim3(32, 8)>>>(Wq, Wk, Wout);
    prepass_kernel<<<dim3(LL / TL, BB), DD>>>(x, P0, lg, cf);

    cudaLaunchConfig_t cfg = {};
    cfg.gridDim = dim3(CS * BB, 1, 1);
    cfg.blockDim = dim3(256, 1, 1);
    cfg.dynamicSmemBytes = SCAN_SMEM;
    cfg.stream = 0;
    cudaLaunchAttribute attrs[1];
    attrs[0].id = cudaLaunchAttributeClusterDimension;
    attrs[0].val.clusterDim.x = CS;
    attrs[0].val.clusterDim.y = 1;
    attrs[0].val.clusterDim.z = 1;
    cfg.attrs = attrs;
    cfg.numAttrs = 1;
    cudaLaunchKernelEx(&cfg, scan_kernel, x, M0, S0);

    postpass_kernel<<<dim3(LL / TL, BB), DD>>>(bout, out);
}

// round 6
// speedup vs baseline: 5.5761x; 1.7120x over previous
#include <cuda_runtime.h>
#include <math.h>
#include <stdint.h>

#define BB 16
#define LL 512
#define DD 128
#define EPSN 1e-12f
#define TL 16
#define CS 4
#define RK 32
#define PP 129                    // odd pitch: conflict-free rows AND columns (scalar access)

#define A1 0.9f
#define A2 0.81f
#define A3 0.729f

// Scratch (device globals; no allocation allowed)
__device__ float g_kphi[BB * LL * DD];
__device__ float g_qphi[BB * LL * DD];
__device__ float g_y[BB * LL * DD];
__device__ float g_WqT[DD * DD];
__device__ float g_WkT[DD * DD];
__device__ float g_WoT[DD * DD];

// ---------------- PTX helpers ----------------
__device__ __forceinline__ uint32_t smem_u32(const void* p) {
    uint32_t a;
    asm("{ .reg .u64 t; cvta.to.shared.u64 t, %1; cvt.u32.u64 %0, t; }" : "=r"(a) : "l"(p));
    return a;
}
__device__ __forceinline__ uint32_t cluster_rank() {
    uint32_t r;
    asm("mov.u32 %0, %%cluster_ctarank;" : "=r"(r));
    return r;
}
#define CARRIVE() asm volatile("barrier.cluster.arrive.aligned;" ::: "memory")
#define CWAIT()   asm volatile("barrier.cluster.wait.aligned;" ::: "memory")

__device__ __forceinline__ void peer_store_f32(uint32_t laddr, uint32_t prank, float v) {
    uint32_t paddr;
    asm volatile("mapa.shared::cluster.u32 %0, %1, %2;" : "=r"(paddr) : "r"(laddr), "r"(prank));
    asm volatile("st.shared::cluster.b32 [%0], %1;" :: "r"(paddr), "r"(__float_as_uint(v)) : "memory");
}

// ---------------- transpose Wq/Wk/Wout ----------------
__global__ void transpose_k(const float* __restrict__ Wq,
                            const float* __restrict__ Wk,
                            const float* __restrict__ Wo) {
    __shared__ float tb[32][33];
    const float* src = blockIdx.z == 0 ? Wq : (blockIdx.z == 1 ? Wk : Wo);
    float* dst = blockIdx.z == 0 ? g_WqT : (blockIdx.z == 1 ? g_WkT : g_WoT);
    int tx = threadIdx.x, ty = threadIdx.y;
    int bx = blockIdx.x * 32, by = blockIdx.y * 32;
#pragma unroll
    for (int j = 0; j < 32; j += 8) tb[ty + j][tx] = src[(by + ty + j) * DD + bx + tx];
    __syncthreads();
#pragma unroll
    for (int j = 0; j < 32; j += 8) dst[(bx + ty + j) * DD + by + tx] = tb[tx][ty + j];
}

// ---------------- prepass ----------------
__global__ __launch_bounds__(DD)
void prepass_kernel(const float* __restrict__ x,
                    const float* __restrict__ P0,
                    const float* __restrict__ log_gain,
                    const float* __restrict__ coeffs) {
    const int b = blockIdx.y, l0 = blockIdx.x * TL;
    const int e = threadIdx.x;
    __shared__ float xs[TL][DD];
    __shared__ float qs[TL][DD];
    __shared__ float rn[TL];

    const float* xp = x + (b * LL + l0) * DD;
#pragma unroll
    for (int tt = 0; tt < TL; ++tt) xs[tt][e] = xp[tt * DD + e];
    __syncthreads();

    float qa[TL], ka[TL];
#pragma unroll
    for (int tt = 0; tt < TL; ++tt) { qa[tt] = 0.f; ka[tt] = 0.f; }
    for (int d = 0; d < DD; ++d) {
        float wq = g_WqT[d * DD + e], wk = g_WkT[d * DD + e];
#pragma unroll
        for (int tt = 0; tt < TL; ++tt) {
            float xv = xs[tt][d];
            qa[tt] += xv * wq;
            ka[tt] += xv * wk;
        }
    }
#pragma unroll
    for (int tt = 0; tt < TL; ++tt) qs[tt][e] = qa[tt];
    __syncthreads();
#pragma unroll
    for (int tt = 0; tt < TL; ++tt) xs[tt][e] = ka[tt] * ka[tt];
    __syncthreads();
    {
        const int w = e >> 5, l = e & 31;
#pragma unroll
        for (int i = 0; i < 4; ++i) {
            int tt = w * 4 + i;
            float v = xs[tt][l] + xs[tt][l + 32] + xs[tt][l + 64] + xs[tt][l + 96];
#pragma unroll
            for (int o = 16; o; o >>= 1) v += __shfl_xor_sync(0xffffffffu, v, o);
            if (l == 0) rn[tt] = 1.0f / fmaxf(sqrtf(v), EPSN);
        }
    }
    __syncthreads();

    float qp[TL];
#pragma unroll
    for (int tt = 0; tt < TL; ++tt) qp[tt] = 0.f;
    for (int d = 0; d < DD; ++d) {
        float p = P0[d * DD + e];
#pragma unroll
        for (int tt = 0; tt < TL; ++tt) qp[tt] += qs[tt][d] * p;
    }
    const float gain = expf(log_gain[e]);
    const float c0 = coeffs[0], c1 = coeffs[1];
#pragma unroll
    for (int tt = 0; tt < TL; ++tt) {
        float kn = ka[tt] * rn[tt];
        g_kphi[(b * LL + l0 + tt) * DD + e] = c0 * kn + c1 * kn * kn;
        float qv = tanhf(gain * qp[tt]);
        g_qphi[(b * LL + l0 + tt) * DD + e] = c0 * qv + c1 * qv * qv;
    }
}

// ---------------- postpass ----------------
__global__ __launch_bounds__(DD)
void postpass_kernel(const float* __restrict__ bout, float* __restrict__ out) {
    const int b = blockIdx.y, l0 = blockIdx.x * TL;
    const int e = threadIdx.x;
    __shared__ float ys[TL][DD];
#pragma unroll
    for (int tt = 0; tt < TL; ++tt) ys[tt][e] = g_y[(b * LL + l0 + tt) * DD + e];
    __syncthreads();
    float acc[TL];
#pragma unroll
    for (int tt = 0; tt < TL; ++tt) acc[tt] = 0.f;
    for (int d = 0; d < DD; ++d) {
        float w = g_WoT[d * DD + e];
#pragma unroll
        for (int tt = 0; tt < TL; ++tt) acc[tt] += ys[tt][d] * w;
    }
    const float bo = bout[e];
#pragma unroll
    for (int tt = 0; tt < TL; ++tt) out[(b * LL + l0 + tt) * DD + e] = acc[tt] + bo;
}

// ---------------- scan: rank-structured recurrence, 4-CTA cluster ----------------
// smem float offsets
#define OFF_S   0                         // 32*PP strip of S
#define OFF_Tm  (32*PP)                   // T strip
#define OFF_U   (64*PP)                   // U strip
#define OFF_S0  (96*PP)                   // full S0 (init only), 128*PP
#define OFF_EB  (96*PP + 128*PP)          // e buf [2][128]
#define OFF_VB  (OFF_EB + 256)            // v buf [2][128]
#define OFF_WP  (OFF_VB + 256)            // w partials [2][4][128]
#define OFF_ZP  (OFF_WP + 1024)
#define OFF_UP  (OFF_ZP + 1024)
#define OFF_WA  (OFF_UP + 1024)           // assembled w [128]
#define OFF_ZA  (OFF_WA + 128)
#define OFF_UA  (OFF_ZA + 128)
#define OFF_KB  (OFF_UA + 128)            // k buf [2][128]
#define OFF_QS  (OFF_KB + 256)            // q [128]
#define OFF_XN  (OFF_QS + 128)            // x next [2][128]
#define OFF_YP  (OFF_XN + 256)            // y partials [32][9]
#define OFF_PR  (OFF_YP + 288)            // pred partials
#define OFF_VP  (OFF_PR + 288)            // v partials
#define OFF_EN  (OFF_VP + 288)            // e-next strip [32]
#define OFF_VNL (OFF_EN + 32)             // v-next strip [32]
#define OFF_SC  (OFF_VNL + 32)            // scalars [8]
#define SCAN_FLOATS (OFF_SC + 8)
#define SCAN_SMEM (SCAN_FLOATS * 4)

__global__ __launch_bounds__(256, 1)
void scan_kernel(const float* __restrict__ x,
                 const float* __restrict__ M0,
                 const float* __restrict__ S0) {
    extern __shared__ float sm[];
    float* Ss  = sm + OFF_S;
    float* Ts  = sm + OFF_Tm;
    float* Us  = sm + OFF_U;
    float* S0s = sm + OFF_S0;
    float* eb  = sm + OFF_EB;
    float* vb  = sm + OFF_VB;
    float* wa  = sm + OFF_WA;
    float* za  = sm + OFF_ZA;
    float* ua  = sm + OFF_UA;
    float* kb  = sm + OFF_KB;
    float* qs  = sm + OFF_QS;
    float* xn  = sm + OFF_XN;
    float* yp  = sm + OFF_YP;
    float* prp = sm + OFF_PR;
    float* vp  = sm + OFF_VP;
    float* en  = sm + OFF_EN;
    float* vnl = sm + OFF_VNL;
    float* sc  = sm + OFF_SC;

    const uint32_t sbase = smem_u32(sm);
    const int tid = threadIdx.x;
    const int lane = tid & 31;           // local row within strip
    const int cg = tid >> 5;             // 16-col group
    const uint32_t rk = cluster_rank();
    const int batch = blockIdx.x >> 2;
    const int rbase = (int)rk * RK;

    const float* kphi = g_kphi + batch * LL * DD;
    const float* qphi = g_qphi + batch * LL * DD;
    const float* xb = x + batch * LL * DD;
    float* yb = g_y + batch * LL * DD;

    // ---------- init ----------
    // full S0 into smem (pitch PP)
    for (int i = tid; i < DD * DD; i += 256) {
        int r = i >> 7, c = i & 127;
        S0s[r * PP + c] = S0[i];
    }
    if (tid < DD) {
        kb[tid] = kphi[tid];                  // k_0
        kb[DD + tid] = kphi[DD + tid];        // k_1
        qs[tid] = qphi[tid];                  // q_0
        xn[tid] = xb[DD + tid];               // x_1 (parity 0)
    }
    // M strip in registers
    float m[16];
#pragma unroll
    for (int j = 0; j < 16; ++j) m[j] = M0[(rbase + lane) * DD + cg * 16 + j];
    __syncthreads();

    // sigma0 (deterministic: partials then warp-0 fixed-order sum)
    {
        float ps = 0.f;
        for (int i = 0; i < 64; ++i) {
            int idx = tid + i * 256;
            int r = idx >> 7, c = idx & 127;
            float v = S0s[r * PP + c];
            ps += v * v;
        }
        yp[tid >= 256 ? 0 : 0] = 0.f;   // no-op keep
        prp[tid] = ps;                  // reuse prp[256] as scratch
    }
    __syncthreads();
    if (tid < 32) {
        float s = 0.f;
#pragma unroll
        for (int j = 0; j < 8; ++j) s += prp[tid * 8 + j];
#pragma unroll
        for (int o = 16; o; o >>= 1) s += __shfl_xor_sync(0xffffffffu, s, o);
        if (tid == 0) sc[3] = s;
    }
    __syncthreads();
    float sig = sc[3];

    // S strip copy
    for (int i = tid; i < RK * DD; i += 256) {
        int r = i >> 7, c = i & 127;
        Ss[r * PP + c] = S0s[(rbase + r) * PP + c];
    }
    __syncthreads();
    // T0/U0 strips
    if (sig != 0.0f) {
#pragma unroll 1
        for (int j = 0; j < 16; ++j) {
            int c = cg * 16 + j;
            float acc = 0.f;
            for (int k = 0; k < DD; ++k)
                acc += S0s[(rbase + lane) * PP + k] * S0s[c * PP + k];
            Ts[lane * PP + c] = acc;
        }
        __syncthreads();
#pragma unroll 1
        for (int j = 0; j < 16; ++j) {
            int c = cg * 16 + j;
            float acc = 0.f;
            for (int k = 0; k < DD; ++k)
                acc += Ts[lane * PP + k] * S0s[k * PP + c];
            Us[lane * PP + c] = acc;
        }
    } else {
        for (int i = tid; i < RK * DD; i += 256) {
            int r = i >> 7, c = i & 127;
            Ts[r * PP + c] = 0.f;
            Us[r * PP + c] = 0.f;
        }
    }
    __syncthreads();

    // e0 = M0 k0 - x0 ; v0 = S0 k0 (strip partials)
    {
        float pr = 0.f, vv = 0.f;
        const int base = lane * PP + cg * 16;
#pragma unroll
        for (int j = 0; j < 16; ++j) {
            float kc = kb[cg * 16 + j];
            pr += m[j] * kc;
            vv += Ss[base + j] * kc;
        }
        prp[lane * 9 + cg] = pr;
        vp[lane * 9 + cg] = vv;
    }
    __syncthreads();
    if (tid < 32) {
        float s = 0.f;
#pragma unroll
        for (int j = 0; j < 8; ++j) s += prp[tid * 9 + j];
        float e = s - xb[rbase + tid];
        en[tid] = e;
        uint32_t la = sbase + (OFF_EB + rbase + tid) * 4;
#pragma unroll
        for (uint32_t pr4 = 0; pr4 < CS; ++pr4) peer_store_f32(la, pr4, e);
    } else if (tid < 64) {
        int i = tid - 32;
        float s = 0.f;
#pragma unroll
        for (int j = 0; j < 8; ++j) s += vp[i * 9 + j];
        vnl[i] = s;
        uint32_t la = sbase + (OFF_VB + rbase + i) * 4;
#pragma unroll
        for (uint32_t pr4 = 0; pr4 < CS; ++pr4) peer_store_f32(la, pr4, s);
    }
    __syncthreads();
    // w/z/u2 partials for t=0 (column pass over strips)
    {
        int c = tid >> 1, h = tid & 1;
        float wp0 = 0.f, zp0 = 0.f, up0 = 0.f;
#pragma unroll
        for (int i = 0; i < 16; ++i) {
            int r = h * 16 + i;
            float s = Ss[r * PP + c];
            wp0 += s * en[r];
            zp0 += s * vnl[r];
            up0 += Ts[r * PP + c] * en[r];
        }
        wp0 += __shfl_xor_sync(0xffffffffu, wp0, 1);
        zp0 += __shfl_xor_sync(0xffffffffu, zp0, 1);
        up0 += __shfl_xor_sync(0xffffffffu, up0, 1);
        if (h == 0) {
            uint32_t lw = sbase + (OFF_WP + (int)rk * 128 + c) * 4;
            uint32_t lz = sbase + (OFF_ZP + (int)rk * 128 + c) * 4;
            uint32_t lu = sbase + (OFF_UP + (int)rk * 128 + c) * 4;
#pragma unroll
            for (uint32_t pr4 = 0; pr4 < CS; ++pr4) {
                peer_store_f32(lw, pr4, wp0);
                peer_store_f32(lz, pr4, zp0);
                peer_store_f32(lu, pr4, up0);
            }
        }
    }
    CARRIVE();

    // ---------- main loop ----------
    for (int t = 0; t < LL; ++t) {
        const int p = t & 1;
        CWAIT();

        // phase 1: assemble w,z,u2 + scalars
        for (int i = tid; i < 384; i += 256) {
            int c = i & 127, a_ = i >> 7;
            int srco = (a_ == 0 ? OFF_WP : (a_ == 1 ? OFF_ZP : OFF_UP)) + p * 512 + c;
            float s = sm[srco] + sm[srco + 128] + sm[srco + 256] + sm[srco + 384];
            sm[(a_ == 0 ? OFF_WA : (a_ == 1 ? OFF_ZA : OFF_UA)) + c] = s;
        }
        if (cg < 3) {
            const float* va = (cg == 0) ? (kb + p * DD) : (eb + p * DD);
            const float* vb2 = (cg == 2) ? (vb + p * DD) : va;
            float s = 0.f;
#pragma unroll
            for (int i = 0; i < 4; ++i) {
                int idx = lane + i * 32;
                s += va[idx] * vb2[idx];
            }
#pragma unroll
            for (int o = 16; o; o >>= 1) s += __shfl_xor_sync(0xffffffffu, s, o);
            if (lane == 0) sc[cg] = s;
        }
        __syncthreads();

        const float kappa = sc[0], eps = sc[1], nu = sc[2];
        sig = A2 * sig + 2.0f * A1 * nu + kappa * eps;
        const float nrm = sqrtf(sig) + 1e-6f;
        const float cSc = 0.015f / nrm;
        const float cUc = 0.005f / (nrm * nrm * nrm);

        // phase 2: fused strip updates + M + matvec partials
        {
            const float e_r = eb[p * DD + rbase + lane];
            const float v_r = vb[p * DD + rbase + lane];
            const float u2r = ua[rbase + lane];
            const float p_r = A2 * u2r + A1 * eps * v_r + (A1 * nu + kappa * eps) * e_r;
            const float alpha = A1 * v_r + kappa * e_r;
            const float beta = A1 * e_r;
            const float gamma = A2 * v_r;
            const float akap = A1 * kappa;
            const float* kcur = kb + p * DD;
            const float* knx = kb + (p ^ 1) * DD;
            const float* ecol = eb + p * DD;
            const float* vcol = vb + p * DD;
            float yv = 0.f, prv = 0.f, vnv = 0.f;
            const int base = lane * PP + cg * 16;
            const int c0 = cg * 16;
#pragma unroll
            for (int j = 0; j < 16; ++j) {
                int c = c0 + j;
                float kc = kcur[c], ec = ecol[c], vc = vcol[c];
                float wc = wa[c], zc = za[c];
                float Sn = A1 * Ss[base + j] + e_r * kc;
                float Tn = A2 * Ts[base + j] + alpha * ec + beta * vc;
                float Un = A3 * Us[base + j] + p_r * kc + gamma * wc + e_r * (A2 * zc + akap * wc);
                float mn = 0.99f * m[j] - cSc * Sn + cUc * Un;
                m[j] = mn;
                yv += mn * qs[c];
                prv += mn * knx[c];
                vnv += Sn * knx[c];
                Ss[base + j] = Sn;
                Ts[base + j] = Tn;
                Us[base + j] = Un;
            }
            yp[lane * 9 + cg] = yv;
            prp[lane * 9 + cg] = prv;
            vp[lane * 9 + cg] = vnv;
        }
        __syncthreads();

        // phase 3: reductions + staging
        if (tid < 32) {
            float s = 0.f;
#pragma unroll
            for (int j = 0; j < 8; ++j) s += yp[tid * 9 + j];
            yb[t * DD + rbase + tid] = s;
        } else if (tid < 64) {
            int i = tid - 32;
            float s = 0.f;
#pragma unroll
            for (int j = 0; j < 8; ++j) s += prp[i * 9 + j];
            float e = s - xn[p * DD + rbase + i];
            en[i] = e;
            if (t + 1 < LL) {
                uint32_t la = sbase + (OFF_EB + (p ^ 1) * DD + rbase + i) * 4;
#pragma unroll
                for (uint32_t pr4 = 0; pr4 < CS; ++pr4) peer_store_f32(la, pr4, e);
            }
        } else if (tid < 96) {
            int i = tid - 64;
            float s = 0.f;
#pragma unroll
            for (int j = 0; j < 8; ++j) s += vp[i * 9 + j];
            vnl[i] = s;
            if (t + 1 < LL) {
                uint32_t la = sbase + (OFF_VB + (p ^ 1) * DD + rbase + i) * 4;
#pragma unroll
                for (uint32_t pr4 = 0; pr4 < CS; ++pr4) peer_store_f32(la, pr4, s);
            }
        } else if (tid < 224) {
            int i = tid - 96;
            int t1 = (t + 1 < LL) ? t + 1 : LL - 1;
            int t2 = (t + 2 < LL) ? t + 2 : LL - 1;
            qs[i] = qphi[t1 * DD + i];
            xn[(p ^ 1) * DD + i] = xb[t2 * DD + i];
            kb[p * DD + i] = kphi[t2 * DD + i];
        }
        __syncthreads();

        // phase 4: next-step column partials + exchange
        if (t + 1 < LL) {
            int c = tid >> 1, h = tid & 1;
            float wp0 = 0.f, zp0 = 0.f, up0 = 0.f;
#pragma unroll
            for (int i = 0; i < 16; ++i) {
                int r = h * 16 + i;
                float s = Ss[r * PP + c];
                wp0 += s * en[r];
                zp0 += s * vnl[r];
                up0 += Ts[r * PP + c] * en[r];
            }
            wp0 += __shfl_xor_sync(0xffffffffu, wp0, 1);
            zp0 += __shfl_xor_sync(0xffffffffu, zp0, 1);
            up0 += __shfl_xor_sync(0xffffffffu, up0, 1);
            if (h == 0) {
                int pb = (p ^ 1) * 512 + (int)rk * 128 + c;
                uint32_t lw = sbase + (OFF_WP + pb) * 4;
                uint32_t lz = sbase + (OFF_ZP + pb) * 4;
                uint32_t lu = sbase + (OFF_UP + pb) * 4;
#pragma unroll
                for (uint32_t pr4 = 0; pr4 < CS; ++pr4) {
                    peer_store_f32(lw, pr4, wp0);
                    peer_store_f32(lz, pr4, zp0);
                    peer_store_f32(lu, pr4, up0);
                }
            }
            CARRIVE();
        }
    }
}

// ---------------- harness entry ----------------
extern "C" void kernel_launch(void* const* d_in, const int* in_sizes, int n_in,
                              void* d_out, int out_size) {
    const float* x    = (const float*)d_in[0];
    const float* Wq   = (const float*)d_in[1];
    const float* Wk   = (const float*)d_in[2];
    const float* P0   = (const float*)d_in[3];
    const float* M0   = (const float*)d_in[4];
    const float* S0   = (const float*)d_in[5];
    const float* lg   = (const float*)d_in[6];
    const float* cf   = (const float*)d_in[7];
    const float* Wout = (const float*)d_in[8];
    const float* bout = (const float*)d_in[9];
    float* out = (float*)d_out;

    cudaFuncSetAttribute(scan_kernel, cudaFuncAttributeMaxDynamicSharedMemorySize, SCAN_SMEM);

    transpose_k<<<dim3(4, 4, 3), dim3(32, 8)>>>(Wq, Wk, Wout);
    prepass_kernel<<<dim3(LL / TL, BB), DD>>>(x, P0, lg, cf);

    cudaLaunchConfig_t cfg = {};
    cfg.gridDim = dim3(CS * BB, 1, 1);
    cfg.blockDim = dim3(256, 1, 1);
    cfg.dynamicSmemBytes = SCAN_SMEM;
    cfg.stream = 0;
    cudaLaunchAttribute attrs[1];
    attrs[0].id = cudaLaunchAttributeClusterDimension;
    attrs[0].val.clusterDim.x = CS;
    attrs[0].val.clusterDim.y = 1;
    attrs[0].val.clusterDim.z = 1;
    cfg.attrs = attrs;
    cfg.numAttrs = 1;
    cudaLaunchKernelEx(&cfg, scan_kernel, x, M0, S0);

    postpass_kernel<<<dim3(LL / TL, BB), DD>>>(bout, out);
}

// round 7
// speedup vs baseline: 5.5764x; 1.0001x over previous
#include <cuda_runtime.h>
#include <math.h>
#include <stdint.h>

#define BB 16
#define LL 512
#define DD 128
#define EPSN 1e-12f
#define TL 16
#define CS 4
#define RK 32
#define PP 129                    // odd pitch: conflict-free rows AND columns (scalar access)

#define A1 0.9f
#define A2 0.81f
#define A3 0.729f

// Scratch (device globals; no allocation allowed)
__device__ float g_kphi[BB * LL * DD];
__device__ float g_qphi[BB * LL * DD];
__device__ float g_y[BB * LL * DD];
__device__ float g_WqT[DD * DD];
__device__ float g_WkT[DD * DD];
__device__ float g_WoT[DD * DD];

// ---------------- PTX helpers ----------------
__device__ __forceinline__ uint32_t smem_u32(const void* p) {
    uint32_t a;
    asm("{ .reg .u64 t; cvta.to.shared.u64 t, %1; cvt.u32.u64 %0, t; }" : "=r"(a) : "l"(p));
    return a;
}
__device__ __forceinline__ uint32_t cluster_rank() {
    uint32_t r;
    asm("mov.u32 %0, %%cluster_ctarank;" : "=r"(r));
    return r;
}
#define CARRIVE() asm volatile("barrier.cluster.arrive.aligned;" ::: "memory")
#define CWAIT()   asm volatile("barrier.cluster.wait.aligned;" ::: "memory")

__device__ __forceinline__ void peer_store_f32(uint32_t laddr, uint32_t prank, float v) {
    uint32_t paddr;
    asm volatile("mapa.shared::cluster.u32 %0, %1, %2;" : "=r"(paddr) : "r"(laddr), "r"(prank));
    asm volatile("st.shared::cluster.b32 [%0], %1;" :: "r"(paddr), "r"(__float_as_uint(v)) : "memory");
}

// ---------------- transpose Wq/Wk/Wout ----------------
__global__ void transpose_k(const float* __restrict__ Wq,
                            const float* __restrict__ Wk,
                            const float* __restrict__ Wo) {
    __shared__ float tb[32][33];
    const float* src = blockIdx.z == 0 ? Wq : (blockIdx.z == 1 ? Wk : Wo);
    float* dst = blockIdx.z == 0 ? g_WqT : (blockIdx.z == 1 ? g_WkT : g_WoT);
    int tx = threadIdx.x, ty = threadIdx.y;
    int bx = blockIdx.x * 32, by = blockIdx.y * 32;
#pragma unroll
    for (int j = 0; j < 32; j += 8) tb[ty + j][tx] = src[(by + ty + j) * DD + bx + tx];
    __syncthreads();
#pragma unroll
    for (int j = 0; j < 32; j += 8) dst[(bx + ty + j) * DD + by + tx] = tb[tx][ty + j];
}

// ---------------- prepass ----------------
__global__ __launch_bounds__(DD)
void prepass_kernel(const float* __restrict__ x,
                    const float* __restrict__ P0,
                    const float* __restrict__ log_gain,
                    const float* __restrict__ coeffs) {
    const int b = blockIdx.y, l0 = blockIdx.x * TL;
    const int e = threadIdx.x;
    __shared__ float xs[TL][DD];
    __shared__ float qs[TL][DD];
    __shared__ float rn[TL];

    const float* xp = x + (b * LL + l0) * DD;
#pragma unroll
    for (int tt = 0; tt < TL; ++tt) xs[tt][e] = xp[tt * DD + e];
    __syncthreads();

    float qa[TL], ka[TL];
#pragma unroll
    for (int tt = 0; tt < TL; ++tt) { qa[tt] = 0.f; ka[tt] = 0.f; }
    for (int d = 0; d < DD; ++d) {
        float wq = g_WqT[d * DD + e], wk = g_WkT[d * DD + e];
#pragma unroll
        for (int tt = 0; tt < TL; ++tt) {
            float xv = xs[tt][d];
            qa[tt] += xv * wq;
            ka[tt] += xv * wk;
        }
    }
#pragma unroll
    for (int tt = 0; tt < TL; ++tt) qs[tt][e] = qa[tt];
    __syncthreads();
#pragma unroll
    for (int tt = 0; tt < TL; ++tt) xs[tt][e] = ka[tt] * ka[tt];
    __syncthreads();
    {
        const int w = e >> 5, l = e & 31;
#pragma unroll
        for (int i = 0; i < 4; ++i) {
            int tt = w * 4 + i;
            float v = xs[tt][l] + xs[tt][l + 32] + xs[tt][l + 64] + xs[tt][l + 96];
#pragma unroll
            for (int o = 16; o; o >>= 1) v += __shfl_xor_sync(0xffffffffu, v, o);
            if (l == 0) rn[tt] = 1.0f / fmaxf(sqrtf(v), EPSN);
        }
    }
    __syncthreads();

    float qp[TL];
#pragma unroll
    for (int tt = 0; tt < TL; ++tt) qp[tt] = 0.f;
    for (int d = 0; d < DD; ++d) {
        float p = P0[d * DD + e];
#pragma unroll
        for (int tt = 0; tt < TL; ++tt) qp[tt] += qs[tt][d] * p;
    }
    const float gain = expf(log_gain[e]);
    const float c0 = coeffs[0], c1 = coeffs[1];
#pragma unroll
    for (int tt = 0; tt < TL; ++tt) {
        float kn = ka[tt] * rn[tt];
        g_kphi[(b * LL + l0 + tt) * DD + e] = c0 * kn + c1 * kn * kn;
        float qv = tanhf(gain * qp[tt]);
        g_qphi[(b * LL + l0 + tt) * DD + e] = c0 * qv + c1 * qv * qv;
    }
}

// ---------------- postpass ----------------
__global__ __launch_bounds__(DD)
void postpass_kernel(const float* __restrict__ bout, float* __restrict__ out) {
    const int b = blockIdx.y, l0 = blockIdx.x * TL;
    const int e = threadIdx.x;
    __shared__ float ys[TL][DD];
#pragma unroll
    for (int tt = 0; tt < TL; ++tt) ys[tt][e] = g_y[(b * LL + l0 + tt) * DD + e];
    __syncthreads();
    float acc[TL];
#pragma unroll
    for (int tt = 0; tt < TL; ++tt) acc[tt] = 0.f;
    for (int d = 0; d < DD; ++d) {
        float w = g_WoT[d * DD + e];
#pragma unroll
        for (int tt = 0; tt < TL; ++tt) acc[tt] += ys[tt][d] * w;
    }
    const float bo = bout[e];
#pragma unroll
    for (int tt = 0; tt < TL; ++tt) out[(b * LL + l0 + tt) * DD + e] = acc[tt] + bo;
}

// ---------------- scan: rank-structured recurrence, 4-CTA cluster ----------------
// smem float offsets
#define OFF_S   0                         // 32*PP strip of S
#define OFF_Tm  (32*PP)                   // T strip
#define OFF_U   (64*PP)                   // U strip
#define OFF_S0  (96*PP)                   // full S0 (init only), 128*PP
#define OFF_EB  (96*PP + 128*PP)          // e buf [2][128]
#define OFF_VB  (OFF_EB + 256)            // v buf [2][128]
#define OFF_WP  (OFF_VB + 256)            // w partials [2][4][128]
#define OFF_ZP  (OFF_WP + 1024)
#define OFF_UP  (OFF_ZP + 1024)
#define OFF_WA  (OFF_UP + 1024)           // assembled w [128]
#define OFF_ZA  (OFF_WA + 128)
#define OFF_UA  (OFF_ZA + 128)
#define OFF_KB  (OFF_UA + 128)            // k buf [2][128]
#define OFF_QS  (OFF_KB + 256)            // q [128]
#define OFF_XN  (OFF_QS + 128)            // x next [2][128]
#define OFF_YP  (OFF_XN + 256)            // y partials [32][9]
#define OFF_PR  (OFF_YP + 288)            // pred partials
#define OFF_VP  (OFF_PR + 288)            // v partials
#define OFF_EN  (OFF_VP + 288)            // e-next strip [32]
#define OFF_VNL (OFF_EN + 32)             // v-next strip [32]
#define OFF_SC  (OFF_VNL + 32)            // scalars [8]
#define SCAN_FLOATS (OFF_SC + 8)
#define SCAN_SMEM (SCAN_FLOATS * 4)

__global__ __launch_bounds__(256, 1)
void scan_kernel(const float* __restrict__ x,
                 const float* __restrict__ M0,
                 const float* __restrict__ S0) {
    extern __shared__ float sm[];
    float* Ss  = sm + OFF_S;
    float* Ts  = sm + OFF_Tm;
    float* Us  = sm + OFF_U;
    float* S0s = sm + OFF_S0;
    float* eb  = sm + OFF_EB;
    float* vb  = sm + OFF_VB;
    float* wa  = sm + OFF_WA;
    float* za  = sm + OFF_ZA;
    float* ua  = sm + OFF_UA;
    float* kb  = sm + OFF_KB;
    float* qs  = sm + OFF_QS;
    float* xn  = sm + OFF_XN;
    float* yp  = sm + OFF_YP;
    float* prp = sm + OFF_PR;
    float* vp  = sm + OFF_VP;
    float* en  = sm + OFF_EN;
    float* vnl = sm + OFF_VNL;
    float* sc  = sm + OFF_SC;

    const uint32_t sbase = smem_u32(sm);
    const int tid = threadIdx.x;
    const int lane = tid & 31;           // local row within strip
    const int cg = tid >> 5;             // 16-col group
    const uint32_t rk = cluster_rank();
    const int batch = blockIdx.x >> 2;
    const int rbase = (int)rk * RK;

    const float* kphi = g_kphi + batch * LL * DD;
    const float* qphi = g_qphi + batch * LL * DD;
    const float* xb = x + batch * LL * DD;
    float* yb = g_y + batch * LL * DD;

    // ---------- init ----------
    // full S0 into smem (pitch PP)
    for (int i = tid; i < DD * DD; i += 256) {
        int r = i >> 7, c = i & 127;
        S0s[r * PP + c] = S0[i];
    }
    if (tid < DD) {
        kb[tid] = kphi[tid];                  // k_0
        kb[DD + tid] = kphi[DD + tid];        // k_1
        qs[tid] = qphi[tid];                  // q_0
        xn[tid] = xb[DD + tid];               // x_1 (parity 0)
    }
    // M strip in registers
    float m[16];
#pragma unroll
    for (int j = 0; j < 16; ++j) m[j] = M0[(rbase + lane) * DD + cg * 16 + j];
    __syncthreads();

    // sigma0 (deterministic: partials then warp-0 fixed-order sum)
    {
        float ps = 0.f;
        for (int i = 0; i < 64; ++i) {
            int idx = tid + i * 256;
            int r = idx >> 7, c = idx & 127;
            float v = S0s[r * PP + c];
            ps += v * v;
        }
        yp[tid >= 256 ? 0 : 0] = 0.f;   // no-op keep
        prp[tid] = ps;                  // reuse prp[256] as scratch
    }
    __syncthreads();
    if (tid < 32) {
        float s = 0.f;
#pragma unroll
        for (int j = 0; j < 8; ++j) s += prp[tid * 8 + j];
#pragma unroll
        for (int o = 16; o; o >>= 1) s += __shfl_xor_sync(0xffffffffu, s, o);
        if (tid == 0) sc[3] = s;
    }
    __syncthreads();
    float sig = sc[3];

    // S strip copy
    for (int i = tid; i < RK * DD; i += 256) {
        int r = i >> 7, c = i & 127;
        Ss[r * PP + c] = S0s[(rbase + r) * PP + c];
    }
    __syncthreads();
    // T0/U0 strips
    if (sig != 0.0f) {
#pragma unroll 1
        for (int j = 0; j < 16; ++j) {
            int c = cg * 16 + j;
            float acc = 0.f;
            for (int k = 0; k < DD; ++k)
                acc += S0s[(rbase + lane) * PP + k] * S0s[c * PP + k];
            Ts[lane * PP + c] = acc;
        }
        __syncthreads();
#pragma unroll 1
        for (int j = 0; j < 16; ++j) {
            int c = cg * 16 + j;
            float acc = 0.f;
            for (int k = 0; k < DD; ++k)
                acc += Ts[lane * PP + k] * S0s[k * PP + c];
            Us[lane * PP + c] = acc;
        }
    } else {
        for (int i = tid; i < RK * DD; i += 256) {
            int r = i >> 7, c = i & 127;
            Ts[r * PP + c] = 0.f;
            Us[r * PP + c] = 0.f;
        }
    }
    __syncthreads();

    // e0 = M0 k0 - x0 ; v0 = S0 k0 (strip partials)
    {
        float pr = 0.f, vv = 0.f;
        const int base = lane * PP + cg * 16;
#pragma unroll
        for (int j = 0; j < 16; ++j) {
            float kc = kb[cg * 16 + j];
            pr += m[j] * kc;
            vv += Ss[base + j] * kc;
        }
        prp[lane * 9 + cg] = pr;
        vp[lane * 9 + cg] = vv;
    }
    __syncthreads();
    if (tid < 32) {
        float s = 0.f;
#pragma unroll
        for (int j = 0; j < 8; ++j) s += prp[tid * 9 + j];
        float e = s - xb[rbase + tid];
        en[tid] = e;
        uint32_t la = sbase + (OFF_EB + rbase + tid) * 4;
#pragma unroll
        for (uint32_t pr4 = 0; pr4 < CS; ++pr4) peer_store_f32(la, pr4, e);
    } else if (tid < 64) {
        int i = tid - 32;
        float s = 0.f;
#pragma unroll
        for (int j = 0; j < 8; ++j) s += vp[i * 9 + j];
        vnl[i] = s;
        uint32_t la = sbase + (OFF_VB + rbase + i) * 4;
#pragma unroll
        for (uint32_t pr4 = 0; pr4 < CS; ++pr4) peer_store_f32(la, pr4, s);
    }
    __syncthreads();
    // w/z/u2 partials for t=0 (column pass over strips)
    {
        int c = tid >> 1, h = tid & 1;
        float wp0 = 0.f, zp0 = 0.f, up0 = 0.f;
#pragma unroll
        for (int i = 0; i < 16; ++i) {
            int r = h * 16 + i;
            float s = Ss[r * PP + c];
            wp0 += s * en[r];
            zp0 += s * vnl[r];
            up0 += Ts[r * PP + c] * en[r];
        }
        wp0 += __shfl_xor_sync(0xffffffffu, wp0, 1);
        zp0 += __shfl_xor_sync(0xffffffffu, zp0, 1);
        up0 += __shfl_xor_sync(0xffffffffu, up0, 1);
        if (h == 0) {
            uint32_t lw = sbase + (OFF_WP + (int)rk * 128 + c) * 4;
            uint32_t lz = sbase + (OFF_ZP + (int)rk * 128 + c) * 4;
            uint32_t lu = sbase + (OFF_UP + (int)rk * 128 + c) * 4;
#pragma unroll
            for (uint32_t pr4 = 0; pr4 < CS; ++pr4) {
                peer_store_f32(lw, pr4, wp0);
                peer_store_f32(lz, pr4, zp0);
                peer_store_f32(lu, pr4, up0);
            }
        }
    }
    CARRIVE();

    // ---------- main loop ----------
    for (int t = 0; t < LL; ++t) {
        const int p = t & 1;
        CWAIT();

        // phase 1: assemble w,z,u2 + scalars
        for (int i = tid; i < 384; i += 256) {
            int c = i & 127, a_ = i >> 7;
            int srco = (a_ == 0 ? OFF_WP : (a_ == 1 ? OFF_ZP : OFF_UP)) + p * 512 + c;
            float s = sm[srco] + sm[srco + 128] + sm[srco + 256] + sm[srco + 384];
            sm[(a_ == 0 ? OFF_WA : (a_ == 1 ? OFF_ZA : OFF_UA)) + c] = s;
        }
        if (cg < 3) {
            const float* va = (cg == 0) ? (kb + p * DD) : (eb + p * DD);
            const float* vb2 = (cg == 2) ? (vb + p * DD) : va;
            float s = 0.f;
#pragma unroll
            for (int i = 0; i < 4; ++i) {
                int idx = lane + i * 32;
                s += va[idx] * vb2[idx];
            }
#pragma unroll
            for (int o = 16; o; o >>= 1) s += __shfl_xor_sync(0xffffffffu, s, o);
            if (lane == 0) sc[cg] = s;
        }
        __syncthreads();

        const float kappa = sc[0], eps = sc[1], nu = sc[2];
        sig = A2 * sig + 2.0f * A1 * nu + kappa * eps;
        const float nrm = sqrtf(sig) + 1e-6f;
        const float cSc = 0.015f / nrm;
        const float cUc = 0.005f / (nrm * nrm * nrm);

        // phase 2: fused strip updates + M + matvec partials
        {
            const float e_r = eb[p * DD + rbase + lane];
            const float v_r = vb[p * DD + rbase + lane];
            const float u2r = ua[rbase + lane];
            const float p_r = A2 * u2r + A1 * eps * v_r + (A1 * nu + kappa * eps) * e_r;
            const float alpha = A1 * v_r + kappa * e_r;
            const float beta = A1 * e_r;
            const float gamma = A2 * v_r;
            const float akap = A1 * kappa;
            const float* kcur = kb + p * DD;
            const float* knx = kb + (p ^ 1) * DD;
            const float* ecol = eb + p * DD;
            const float* vcol = vb + p * DD;
            float yv = 0.f, prv = 0.f, vnv = 0.f;
            const int base = lane * PP + cg * 16;
            const int c0 = cg * 16;
#pragma unroll
            for (int j = 0; j < 16; ++j) {
                int c = c0 + j;
                float kc = kcur[c], ec = ecol[c], vc = vcol[c];
                float wc = wa[c], zc = za[c];
                float Sn = A1 * Ss[base + j] + e_r * kc;
                float Tn = A2 * Ts[base + j] + alpha * ec + beta * vc;
                float Un = A3 * Us[base + j] + p_r * kc + gamma * wc + e_r * (A2 * zc + akap * wc);
                float mn = 0.99f * m[j] - cSc * Sn + cUc * Un;
                m[j] = mn;
                yv += mn * qs[c];
                prv += mn * knx[c];
                vnv += Sn * knx[c];
                Ss[base + j] = Sn;
                Ts[base + j] = Tn;
                Us[base + j] = Un;
            }
            yp[lane * 9 + cg] = yv;
            prp[lane * 9 + cg] = prv;
            vp[lane * 9 + cg] = vnv;
        }
        __syncthreads();

        // phase 3: reductions + staging
        if (tid < 32) {
            float s = 0.f;
#pragma unroll
            for (int j = 0; j < 8; ++j) s += yp[tid * 9 + j];
            yb[t * DD + rbase + tid] = s;
        } else if (tid < 64) {
            int i = tid - 32;
            float s = 0.f;
#pragma unroll
            for (int j = 0; j < 8; ++j) s += prp[i * 9 + j];
            float e = s - xn[p * DD + rbase + i];
            en[i] = e;
            if (t + 1 < LL) {
                uint32_t la = sbase + (OFF_EB + (p ^ 1) * DD + rbase + i) * 4;
#pragma unroll
                for (uint32_t pr4 = 0; pr4 < CS; ++pr4) peer_store_f32(la, pr4, e);
            }
        } else if (tid < 96) {
            int i = tid - 64;
            float s = 0.f;
#pragma unroll
            for (int j = 0; j < 8; ++j) s += vp[i * 9 + j];
            vnl[i] = s;
            if (t + 1 < LL) {
                uint32_t la = sbase + (OFF_VB + (p ^ 1) * DD + rbase + i) * 4;
#pragma unroll
                for (uint32_t pr4 = 0; pr4 < CS; ++pr4) peer_store_f32(la, pr4, s);
            }
        } else if (tid < 224) {
            int i = tid - 96;
            int t1 = (t + 1 < LL) ? t + 1 : LL - 1;
            int t2 = (t + 2 < LL) ? t + 2 : LL - 1;
            qs[i] = qphi[t1 * DD + i];
            xn[(p ^ 1) * DD + i] = xb[t2 * DD + i];
            kb[p * DD + i] = kphi[t2 * DD + i];
        }
        __syncthreads();

        // phase 4: next-step column partials + exchange
        if (t + 1 < LL) {
            int c = tid >> 1, h = tid & 1;
            float wp0 = 0.f, zp0 = 0.f, up0 = 0.f;
#pragma unroll
            for (int i = 0; i < 16; ++i) {
                int r = h * 16 + i;
                float s = Ss[r * PP + c];
                wp0 += s * en[r];
                zp0 += s * vnl[r];
                up0 += Ts[r * PP + c] * en[r];
            }
            wp0 += __shfl_xor_sync(0xffffffffu, wp0, 1);
            zp0 += __shfl_xor_sync(0xffffffffu, zp0, 1);
            up0 += __shfl_xor_sync(0xffffffffu, up0, 1);
            if (h == 0) {
                int pb = (p ^ 1) * 512 + (int)rk * 128 + c;
                uint32_t lw = sbase + (OFF_WP + pb) * 4;
                uint32_t lz = sbase + (OFF_ZP + pb) * 4;
                uint32_t lu = sbase + (OFF_UP + pb) * 4;
#pragma unroll
                for (uint32_t pr4 = 0; pr4 < CS; ++pr4) {
                    peer_store_f32(lw, pr4, wp0);
                    peer_store_f32(lz, pr4, zp0);
                    peer_store_f32(lu, pr4, up0);
                }
            }
            CARRIVE();
        }
    }
}

// ---------------- harness entry ----------------
extern "C" void kernel_launch(void* const* d_in, const int* in_sizes, int n_in,
                              void* d_out, int out_size) {
    const float* x    = (const float*)d_in[0];
    const float* Wq   = (const float*)d_in[1];
    const float* Wk   = (const float*)d_in[2];
    const float* P0   = (const float*)d_in[3];
    const float* M0   = (const float*)d_in[4];
    const float* S0   = (const float*)d_in[5];
    const float* lg   = (const float*)d_in[6];
    const float* cf   = (const float*)d_in[7];
    const float* Wout = (const float*)d_in[8];
    const float* bout = (const float*)d_in[9];
    float* out = (float*)d_out;

    cudaFuncSetAttribute(scan_kernel, cudaFuncAttributeMaxDynamicSharedMemorySize, SCAN_SMEM);

    transpose_k<<<dim3(4, 4, 3), dim3(32, 8)>>>(Wq, Wk, Wout);
    prepass_kernel<<<dim3(LL / TL, BB), DD>>>(x, P0, lg, cf);

    cudaLaunchConfig_t cfg = {};
    cfg.gridDim = dim3(CS * BB, 1, 1);
    cfg.blockDim = dim3(256, 1, 1);
    cfg.dynamicSmemBytes = SCAN_SMEM;
    cfg.stream = 0;
    cudaLaunchAttribute attrs[1];
    attrs[0].id = cudaLaunchAttributeClusterDimension;
    attrs[0].val.clusterDim.x = CS;
    attrs[0].val.clusterDim.y = 1;
    attrs[0].val.clusterDim.z = 1;
    cfg.attrs = attrs;
    cfg.numAttrs = 1;
    cudaLaunchKernelEx(&cfg, scan_kernel, x, M0, S0);

    postpass_kernel<<<dim3(LL / TL, BB), DD>>>(bout, out);
}